// round 10
// baseline (speedup 1.0000x reference)
#include <cuda_runtime.h>
#include <cuda_bf16.h>
#include <cstdint>
#include <cstddef>

// Problem constants
#define BATCH   2
#define SEQ     2048
#define DMODEL  1024
#define NH      16
#define DH      64
#define MTOT    (BATCH * SEQ)        // 4096 rows
#define NT      512                   // threads per CTA (16 warps)

// ---------------------------------------------------------------------------
// Scratch (device globals; no allocations allowed)
// ---------------------------------------------------------------------------
__device__ __nv_bfloat16 g_xhi [MTOT * DMODEL];
__device__ __nv_bfloat16 g_xlo [MTOT * DMODEL];
__device__ __nv_bfloat16 g_whi [4][DMODEL * DMODEL];
__device__ __nv_bfloat16 g_wlo [4][DMODEL * DMODEL];
__device__ __nv_bfloat16 g_Qhi [MTOT * DMODEL];
__device__ __nv_bfloat16 g_Qlo [MTOT * DMODEL];
__device__ __nv_bfloat16 g_Khi [MTOT * DMODEL];
__device__ __nv_bfloat16 g_Klo [MTOT * DMODEL];
__device__ __nv_bfloat16 g_Vhi [MTOT * DMODEL];
__device__ __nv_bfloat16 g_Vlo [MTOT * DMODEL];
__device__ __nv_bfloat16 g_AOhi[MTOT * DMODEL];
__device__ __nv_bfloat16 g_AOlo[MTOT * DMODEL];

// ---------------------------------------------------------------------------
// Helpers
// ---------------------------------------------------------------------------
__device__ __forceinline__ void mma_bf16(float* c, const uint32_t* a, const uint32_t* b) {
    asm volatile(
        "mma.sync.aligned.m16n8k16.row.col.f32.bf16.bf16.f32 "
        "{%0,%1,%2,%3}, {%4,%5,%6,%7}, {%8,%9}, {%0,%1,%2,%3};"
        : "+f"(c[0]), "+f"(c[1]), "+f"(c[2]), "+f"(c[3])
        : "r"(a[0]), "r"(a[1]), "r"(a[2]), "r"(a[3]),
          "r"(b[0]), "r"(b[1]));
}

__device__ __forceinline__ uint32_t pack2_bf16(float a, float b) {
    __nv_bfloat162 t = __floats2bfloat162_rn(a, b);
    return *(uint32_t*)&t;
}
__device__ __forceinline__ float bf16_hi(float x) {
    return __bfloat162float(__float2bfloat16(x));
}

__device__ __forceinline__ uint32_t smem_u32(const void* p) {
    uint32_t a;
    asm("{ .reg .u64 t; cvta.to.shared.u64 t, %1; cvt.u32.u64 %0, t; }"
        : "=r"(a) : "l"(p));
    return a;
}

__device__ __forceinline__ void cp16(uint32_t dst, const void* src) {
    asm volatile("cp.async.cg.shared.global [%0], [%1], 16;" :: "r"(dst), "l"(src));
}
#define CP_COMMIT() asm volatile("cp.async.commit_group;" ::: "memory")
#define CP_WAIT(n)  asm volatile("cp.async.wait_group %0;" :: "n"(n) : "memory")

__device__ __forceinline__ void ldsm_x4(uint32_t* r, uint32_t addr) {
    asm volatile("ldmatrix.sync.aligned.m8n8.x4.shared.b16 {%0,%1,%2,%3}, [%4];"
        : "=r"(r[0]), "=r"(r[1]), "=r"(r[2]), "=r"(r[3]) : "r"(addr));
}
__device__ __forceinline__ void ldsm_x4_t(uint32_t* r, uint32_t addr) {
    asm volatile("ldmatrix.sync.aligned.m8n8.x4.trans.shared.b16 {%0,%1,%2,%3}, [%4];"
        : "=r"(r[0]), "=r"(r[1]), "=r"(r[2]), "=r"(r[3]) : "r"(addr));
}

// ---------------------------------------------------------------------------
// Split kernel: fp32 -> bf16 hi + bf16 lo residual
// ---------------------------------------------------------------------------
__global__ void split_kernel(const float* __restrict__ src,
                             __nv_bfloat16* __restrict__ hi,
                             __nv_bfloat16* __restrict__ lo, int n4)
{
    int i = blockIdx.x * blockDim.x + threadIdx.x;
    if (i >= n4) return;
    float4 v = ((const float4*)src)[i];
    uint2 h, l;
    h.x = pack2_bf16(v.x, v.y);
    h.y = pack2_bf16(v.z, v.w);
    l.x = pack2_bf16(v.x - bf16_hi(v.x), v.y - bf16_hi(v.y));
    l.y = pack2_bf16(v.z - bf16_hi(v.z), v.w - bf16_hi(v.w));
    ((uint2*)hi)[i] = h;
    ((uint2*)lo)[i] = l;
}

// ===========================================================================
// Split-bf16 GEMM: 512 threads / 16 warps (8M x 2N, warp tile 16x64),
// 3-stage cp.async ring, pass-reordered MMAs.
// ===========================================================================
#define GS 72
#define GT (128 * GS)
#define GEMM_SMEM_B (12 * GT * 2)     // 3 stages x 4 tiles = 221184 B

__global__ __launch_bounds__(NT, 1)
void mma_gemm_kernel(const __nv_bfloat16* __restrict__ Ah,
                     const __nv_bfloat16* __restrict__ Al,
                     const __nv_bfloat16* __restrict__ Wh,
                     const __nv_bfloat16* __restrict__ Wl,
                     const float* __restrict__ b0,
                     const float* __restrict__ b1,
                     const float* __restrict__ b2,
                     __nv_bfloat16* __restrict__ C0h, __nv_bfloat16* __restrict__ C0l,
                     __nv_bfloat16* __restrict__ C1h, __nv_bfloat16* __restrict__ C1l,
                     __nv_bfloat16* __restrict__ C2h, __nv_bfloat16* __restrict__ C2l,
                     float* __restrict__ Cf,
                     int M, int N, int K, int mode)
{
    extern __shared__ __nv_bfloat16 sm[];
    const uint32_t sb = smem_u32(sm);

    const int z = blockIdx.z;
    const __nv_bfloat16* Bh = Wh + (size_t)z * DMODEL * DMODEL;
    const __nv_bfloat16* Bl = Wl + (size_t)z * DMODEL * DMODEL;
    const float* bias = (z == 0) ? b0 : (z == 1) ? b1 : b2;
    __nv_bfloat16* Chi = (z == 0) ? C0h : (z == 1) ? C1h : C2h;
    __nv_bfloat16* Clo = (z == 0) ? C0l : (z == 1) ? C1l : C2l;

    const int t    = threadIdx.x;
    const int wid  = t >> 5;
    const int lane = t & 31;
    const int g    = lane >> 2;
    const int tq   = lane & 3;
    const int q    = lane >> 3;
    const int l8   = lane & 7;
    const int m0   = (wid >> 1) * 16;   // 8 M-warps x 16 rows
    const int n0   = (wid & 1) * 64;    // 2 N-warps x 64 cols

    const int bm = blockIdx.y * 128;
    const int bn = blockIdx.x * 128;

    float acc[8][4];
#pragma unroll
    for (int ni = 0; ni < 8; ni++)
#pragma unroll
        for (int e = 0; e < 4; e++) acc[ni][e] = 0.0f;

    const int NCHUNK = K / 64;    // 16

    auto fill = [&](int c, int s) {
        const int k0 = c * 64;
        const uint32_t stg = s * 4 * GT;
#pragma unroll
        for (int i = 0; i < 2; i++) {
            const int l   = i * NT + t;
            const int row = l >> 3;
            const int seg = l & 7;
            const uint32_t d = sb + 2 * (stg + row * GS + seg * 8);
            const size_t   o  = (size_t)(bm + row) * K + k0 + seg * 8;
            const size_t   ob = (size_t)(bn + row) * K + k0 + seg * 8;
            cp16(d,              Ah + o);
            cp16(d + 2 * GT,     Al + o);
            cp16(d + 2 * 2 * GT, Bh + ob);
            cp16(d + 2 * 3 * GT, Bl + ob);
        }
    };

    fill(0, 0); CP_COMMIT();
    fill(1, 1); CP_COMMIT();

    for (int c = 0; c < NCHUNK; c++) {
        if (c == NCHUNK - 1) { CP_WAIT(0); } else { CP_WAIT(1); }
        __syncthreads();
        if (c + 2 < NCHUNK) { fill(c + 2, (c + 2) % 3); CP_COMMIT(); }

        const uint32_t stg  = (c % 3) * 4 * GT;
        const uint32_t sAhi = sb + 2 * stg;
        const uint32_t sAlo = sAhi + 2 * GT;
        const uint32_t sBhi = sAlo + 2 * GT;
        const uint32_t sBlo = sBhi + 2 * GT;

#pragma unroll
        for (int ks = 0; ks < 4; ks++) {
            const int kk = ks * 16;

            uint32_t ah[4], al[4];
            {
                const int arow = m0 + (q & 1) * 8 + l8;
                const int acol = kk + (q >> 1) * 8;
                ldsm_x4(ah, sAhi + 2 * (arow * GS + acol));
                ldsm_x4(al, sAlo + 2 * (arow * GS + acol));
            }
#pragma unroll
            for (int p = 0; p < 2; p++) {
                uint32_t bh[2][4], bl[2][4];
#pragma unroll
                for (int j = 0; j < 2; j++) {
                    const int np = 2 * p + j;
                    const int brow = n0 + np * 16 + (q >> 1) * 8 + l8;
                    const int bcol = kk + (q & 1) * 8;
                    ldsm_x4(bh[j], sBhi + 2 * (brow * GS + bcol));
                    ldsm_x4(bl[j], sBlo + 2 * (brow * GS + bcol));
                }
                // pass hh (4 independent)
#pragma unroll
                for (int j = 0; j < 2; j++) {
                    const int ni = (2 * p + j) * 2;
                    mma_bf16(acc[ni],     ah, bh[j]);
                    mma_bf16(acc[ni + 1], ah, bh[j] + 2);
                }
                // pass hl
#pragma unroll
                for (int j = 0; j < 2; j++) {
                    const int ni = (2 * p + j) * 2;
                    mma_bf16(acc[ni],     ah, bl[j]);
                    mma_bf16(acc[ni + 1], ah, bl[j] + 2);
                }
                // pass lh
#pragma unroll
                for (int j = 0; j < 2; j++) {
                    const int ni = (2 * p + j) * 2;
                    mma_bf16(acc[ni],     al, bh[j]);
                    mma_bf16(acc[ni + 1], al, bh[j] + 2);
                }
            }
        }
    }

    // Epilogue
    {
        const int r0 = bm + m0 + g;
#pragma unroll
        for (int ni = 0; ni < 8; ni++) {
            const int col = bn + n0 + ni * 8 + 2 * tq;
            const float bb0 = bias[col], bb1 = bias[col + 1];
            float c00 = acc[ni][0] + bb0, c01 = acc[ni][1] + bb1;
            float c10 = acc[ni][2] + bb0, c11 = acc[ni][3] + bb1;
            if (mode == 0) {
                float2 v0 = {c00, c01}, v1 = {c10, c11};
                *(float2*)&Cf[(size_t)r0 * N + col]       = v0;
                *(float2*)&Cf[(size_t)(r0 + 8) * N + col] = v1;
            } else {
                *(uint32_t*)&Chi[(size_t)r0 * N + col] = pack2_bf16(c00, c01);
                *(uint32_t*)&Clo[(size_t)r0 * N + col] =
                    pack2_bf16(c00 - bf16_hi(c00), c01 - bf16_hi(c01));
                *(uint32_t*)&Chi[(size_t)(r0 + 8) * N + col] = pack2_bf16(c10, c11);
                *(uint32_t*)&Clo[(size_t)(r0 + 8) * N + col] =
                    pack2_bf16(c10 - bf16_hi(c10), c11 - bf16_hi(c11));
            }
        }
    }
}

// ===========================================================================
// FA2-style split-bf16 causal attention, 512 threads / 16 warps.
// Warp pair (w, w+8) shares 16 q-rows; w handles S/n cols 0..63, w+8 cols
// 64..127. Phase 2 contracts each warp's own n-half over all 64 d-cols;
// O partials reduced through smem after the kb loop (overlays ring tiles 0/1).
// 3-stage K/V ring; Q tiles 0,1 used in prologue only.
// ===========================================================================
#define ATTN_SMEM_B (12 * GT * 2)     // 221184 B

__global__ __launch_bounds__(NT, 1)
void mma_attn_kernel(const __nv_bfloat16* __restrict__ Qh,
                     const __nv_bfloat16* __restrict__ Ql,
                     const __nv_bfloat16* __restrict__ Kh,
                     const __nv_bfloat16* __restrict__ Kl,
                     const __nv_bfloat16* __restrict__ Vh,
                     const __nv_bfloat16* __restrict__ Vl,
                     __nv_bfloat16* __restrict__ Ohi,
                     __nv_bfloat16* __restrict__ Olo)
{
    extern __shared__ __nv_bfloat16 sm[];
    const uint32_t sb = smem_u32(sm);

    const int qb = (gridDim.x - 1) - blockIdx.x;   // heavy CTAs first
    const int h  = blockIdx.y;
    const int b  = blockIdx.z;

    const int t    = threadIdx.x;
    const int wid  = t >> 5;
    const int lane = t & 31;
    const int g    = lane >> 2;
    const int tq   = lane & 3;
    const int q    = lane >> 3;
    const int l8   = lane & 7;
    const int qw   = wid & 7;           // q-row group 0..7
    const int nh   = wid >> 3;          // n-half 0/1
    const int m0   = qw * 16;
    const int nc0  = nh * 64;           // this warp's S/n column base

    const int hoff  = h * DH;
    const int brow0 = b * SEQ;
    const int qrow0 = brow0 + qb * 128;

    const uint32_t stK[3] = { 2u * GT, 6u * GT, 10u * GT };
    const uint32_t stV[3] = { 4u * GT, 8u * GT, 0u * GT  };

    auto fillKV = [&](int kb, int s) {
        const int krow0 = brow0 + kb * 128;
#pragma unroll
        for (int i = 0; i < 2; i++) {
            const int l   = i * NT + t;
            const int row = l >> 3;
            const int seg = l & 7;
            const uint32_t off = row * GS + seg * 8;
            const size_t   sidx = (size_t)(krow0 + row) * DMODEL + hoff + seg * 8;
            const uint32_t dK = sb + 2 * (stK[s] + off);
            const uint32_t dV = sb + 2 * (stV[s] + off);
            cp16(dK,          Kh + sidx);
            cp16(dK + 2 * GT, Kl + sidx);
            cp16(dV,          Vh + sidx);
            cp16(dV + 2 * GT, Vl + sidx);
        }
    };

    // ---- prologue: Q (tiles 0,1) + KV stage 0; then KV stage 1 ----
#pragma unroll
    for (int i = 0; i < 2; i++) {
        const int l   = i * NT + t;
        const int row = l >> 3;
        const int seg = l & 7;
        const uint32_t d = sb + 2 * (row * GS + seg * 8);
        const size_t   o = (size_t)(qrow0 + row) * DMODEL + hoff + seg * 8;
        cp16(d,          Qh + o);
        cp16(d + 2 * GT, Ql + o);
    }
    fillKV(0, 0);
    CP_COMMIT();
    if (qb >= 1) { fillKV(1, 1); CP_COMMIT(); }

    if (qb >= 1) { CP_WAIT(1); } else { CP_WAIT(0); }
    __syncthreads();

    uint32_t qh[4][4], ql[4][4];
#pragma unroll
    for (int ks = 0; ks < 4; ks++) {
        const int arow = m0 + (q & 1) * 8 + l8;
        const int acol = ks * 16 + (q >> 1) * 8;
        ldsm_x4(qh[ks], sb + 2 * (arow * GS + acol));
        ldsm_x4(ql[ks], sb + 2 * (GT + arow * GS + acol));
    }

    float o[8][4];
#pragma unroll
    for (int ni = 0; ni < 8; ni++)
#pragma unroll
        for (int e = 0; e < 4; e++) o[ni][e] = 0.0f;

    for (int kb = 0; kb <= qb; kb++) {
        if (kb == qb) { CP_WAIT(0); } else { CP_WAIT(1); }
        __syncthreads();
        if (kb + 2 <= qb) { fillKV(kb + 2, (kb + 2) % 3); CP_COMMIT(); }

        const int st = kb % 3;
        const uint32_t sKhi = sb + 2 * stK[st];
        const uint32_t sKlo = sKhi + 2 * GT;
        const uint32_t sVhi = sb + 2 * stV[st];
        const uint32_t sVlo = sVhi + 2 * GT;

        // ---- Phase 1: S[16 x 64] (this warp's n-half) in registers ----
        float s[8][4];
#pragma unroll
        for (int nt = 0; nt < 8; nt++)
#pragma unroll
            for (int e = 0; e < 4; e++) s[nt][e] = 0.0f;

#pragma unroll
        for (int ks = 0; ks < 4; ks++) {
            const int kk = ks * 16;
#pragma unroll
            for (int p = 0; p < 2; p++) {
                uint32_t bh[2][4], bl[2][4];
#pragma unroll
                for (int j = 0; j < 2; j++) {
                    const int ntp = 2 * p + j;
                    const int brow = nc0 + ntp * 16 + (q >> 1) * 8 + l8;
                    const int bcol = kk + (q & 1) * 8;
                    ldsm_x4(bh[j], sKhi + 2 * (brow * GS + bcol));
                    ldsm_x4(bl[j], sKlo + 2 * (brow * GS + bcol));
                }
#pragma unroll
                for (int j = 0; j < 2; j++) {
                    const int nt = (2 * p + j) * 2;
                    mma_bf16(s[nt],     qh[ks], bh[j]);
                    mma_bf16(s[nt + 1], qh[ks], bh[j] + 2);
                }
#pragma unroll
                for (int j = 0; j < 2; j++) {
                    const int nt = (2 * p + j) * 2;
                    mma_bf16(s[nt],     qh[ks], bl[j]);
                    mma_bf16(s[nt + 1], qh[ks], bl[j] + 2);
                }
#pragma unroll
                for (int j = 0; j < 2; j++) {
                    const int nt = (2 * p + j) * 2;
                    mma_bf16(s[nt],     ql[ks], bh[j]);
                    mma_bf16(s[nt + 1], ql[ks], bh[j] + 2);
                }
            }
        }

        // Diagonal-block causal mask: keep col <= row
        if (kb == qb) {
            const int r0 = m0 + g, r1 = m0 + g + 8;
#pragma unroll
            for (int nt = 0; nt < 8; nt++) {
                const int c0 = nc0 + nt * 8 + 2 * tq;
                if (c0     > r0) s[nt][0] = 0.0f;
                if (c0 + 1 > r0) s[nt][1] = 0.0f;
                if (c0     > r1) s[nt][2] = 0.0f;
                if (c0 + 1 > r1) s[nt][3] = 0.0f;
            }
        }

        // ---- Phase 2: O[16 x 64] += S(half) @ V(half rows) ----
#pragma unroll
        for (int kc = 0; kc < 4; kc++) {
            uint32_t ah[4], al[4];
            {
                const float v0 = s[2 * kc][0],     v1 = s[2 * kc][1];
                const float v2 = s[2 * kc][2],     v3 = s[2 * kc][3];
                const float w0 = s[2 * kc + 1][0], w1 = s[2 * kc + 1][1];
                const float w2 = s[2 * kc + 1][2], w3 = s[2 * kc + 1][3];
                ah[0] = pack2_bf16(v0, v1);
                ah[1] = pack2_bf16(v2, v3);
                ah[2] = pack2_bf16(w0, w1);
                ah[3] = pack2_bf16(w2, w3);
                al[0] = pack2_bf16(v0 - bf16_hi(v0), v1 - bf16_hi(v1));
                al[1] = pack2_bf16(v2 - bf16_hi(v2), v3 - bf16_hi(v3));
                al[2] = pack2_bf16(w0 - bf16_hi(w0), w1 - bf16_hi(w1));
                al[3] = pack2_bf16(w2 - bf16_hi(w2), w3 - bf16_hi(w3));
            }
            const int vr = nc0 + kc * 16 + (q & 1) * 8 + l8;
#pragma unroll
            for (int p = 0; p < 2; p++) {
                uint32_t bh[2][4], bl[2][4];
#pragma unroll
                for (int j = 0; j < 2; j++) {
                    const int ntp = 2 * p + j;
                    const int vcol = ntp * 16 + (q >> 1) * 8;
                    ldsm_x4_t(bh[j], sVhi + 2 * (vr * GS + vcol));
                    ldsm_x4_t(bl[j], sVlo + 2 * (vr * GS + vcol));
                }
#pragma unroll
                for (int j = 0; j < 2; j++) {
                    const int ni = (2 * p + j) * 2;
                    mma_bf16(o[ni],     ah, bh[j]);
                    mma_bf16(o[ni + 1], ah, bh[j] + 2);
                }
#pragma unroll
                for (int j = 0; j < 2; j++) {
                    const int ni = (2 * p + j) * 2;
                    mma_bf16(o[ni],     ah, bl[j]);
                    mma_bf16(o[ni + 1], ah, bl[j] + 2);
                }
#pragma unroll
                for (int j = 0; j < 2; j++) {
                    const int ni = (2 * p + j) * 2;
                    mma_bf16(o[ni],     al, bh[j]);
                    mma_bf16(o[ni + 1], al, bh[j] + 2);
                }
            }
        }
    }

    // ---- Reduce O partials across warp pairs (overlay ring tiles 0/1) ----
    __syncthreads();                      // everyone done reading K/V tiles
    float* red = (float*)sm;              // 8 groups x 16 rows x 64 cols fp32 = 32KB
    if (nh == 1) {
#pragma unroll
        for (int ni = 0; ni < 8; ni++) {
            const int col = ni * 8 + 2 * tq;
            float2 v0 = {o[ni][0], o[ni][1]};
            float2 v1 = {o[ni][2], o[ni][3]};
            *(float2*)&red[(qw * 16 + g) * 64 + col]     = v0;
            *(float2*)&red[(qw * 16 + g + 8) * 64 + col] = v1;
        }
    }
    __syncthreads();

    if (nh == 0) {
#pragma unroll
        for (int ni = 0; ni < 8; ni++) {
            const int col = ni * 8 + 2 * tq;
            float2 v0 = *(const float2*)&red[(qw * 16 + g) * 64 + col];
            float2 v1 = *(const float2*)&red[(qw * 16 + g + 8) * 64 + col];
            o[ni][0] += v0.x; o[ni][1] += v0.y;
            o[ni][2] += v1.x; o[ni][3] += v1.y;
        }
        // Epilogue: write split-bf16 AO in concat-head layout
#pragma unroll
        for (int ni = 0; ni < 8; ni++) {
            const int col = hoff + ni * 8 + 2 * tq;
            const size_t r0 = (size_t)(qrow0 + m0 + g) * DMODEL + col;
            const size_t r1 = (size_t)(qrow0 + m0 + g + 8) * DMODEL + col;
            const float c00 = o[ni][0], c01 = o[ni][1];
            const float c10 = o[ni][2], c11 = o[ni][3];
            *(uint32_t*)&Ohi[r0] = pack2_bf16(c00, c01);
            *(uint32_t*)&Olo[r0] = pack2_bf16(c00 - bf16_hi(c00), c01 - bf16_hi(c01));
            *(uint32_t*)&Ohi[r1] = pack2_bf16(c10, c11);
            *(uint32_t*)&Olo[r1] = pack2_bf16(c10 - bf16_hi(c10), c11 - bf16_hi(c11));
        }
    }
}

// ---------------------------------------------------------------------------
// Launch
// ---------------------------------------------------------------------------
extern "C" void kernel_launch(void* const* d_in, const int* in_sizes, int n_in,
                              void* d_out, int out_size)
{
    const float* x    = (const float*)d_in[0];
    const float* wq_w = (const float*)d_in[1];
    const float* wq_b = (const float*)d_in[2];
    const float* wk_w = (const float*)d_in[3];
    const float* wk_b = (const float*)d_in[4];
    const float* wv_w = (const float*)d_in[5];
    const float* wv_b = (const float*)d_in[6];
    const float* wo_w = (const float*)d_in[7];
    const float* wo_b = (const float*)d_in[8];
    float* out = (float*)d_out;

    __nv_bfloat16 *xhi, *xlo, *whi, *wlo;
    __nv_bfloat16 *Qhi, *Qlo, *Khi, *Klo, *Vhi, *Vlo, *AOhi, *AOlo;
    cudaGetSymbolAddress((void**)&xhi,  g_xhi);
    cudaGetSymbolAddress((void**)&xlo,  g_xlo);
    cudaGetSymbolAddress((void**)&whi,  g_whi);
    cudaGetSymbolAddress((void**)&wlo,  g_wlo);
    cudaGetSymbolAddress((void**)&Qhi,  g_Qhi);
    cudaGetSymbolAddress((void**)&Qlo,  g_Qlo);
    cudaGetSymbolAddress((void**)&Khi,  g_Khi);
    cudaGetSymbolAddress((void**)&Klo,  g_Klo);
    cudaGetSymbolAddress((void**)&Vhi,  g_Vhi);
    cudaGetSymbolAddress((void**)&Vlo,  g_Vlo);
    cudaGetSymbolAddress((void**)&AOhi, g_AOhi);
    cudaGetSymbolAddress((void**)&AOlo, g_AOlo);

    cudaFuncSetAttribute(mma_gemm_kernel,
                         cudaFuncAttributeMaxDynamicSharedMemorySize, GEMM_SMEM_B);
    cudaFuncSetAttribute(mma_attn_kernel,
                         cudaFuncAttributeMaxDynamicSharedMemorySize, ATTN_SMEM_B);

    const size_t WW = (size_t)DMODEL * DMODEL;

    split_kernel<<<(MTOT * DMODEL / 4 + 255) / 256, 256>>>(x, xhi, xlo, MTOT * DMODEL / 4);
    split_kernel<<<((int)WW / 4 + 255) / 256, 256>>>(wq_w, whi + 0 * WW, wlo + 0 * WW, WW / 4);
    split_kernel<<<((int)WW / 4 + 255) / 256, 256>>>(wk_w, whi + 1 * WW, wlo + 1 * WW, WW / 4);
    split_kernel<<<((int)WW / 4 + 255) / 256, 256>>>(wv_w, whi + 2 * WW, wlo + 2 * WW, WW / 4);
    split_kernel<<<((int)WW / 4 + 255) / 256, 256>>>(wo_w, whi + 3 * WW, wlo + 3 * WW, WW / 4);

    // Fused Q/K/V projections
    dim3 gqkv(DMODEL / 128, MTOT / 128, 3);
    mma_gemm_kernel<<<gqkv, NT, GEMM_SMEM_B>>>(
        xhi, xlo, whi, wlo, wq_b, wk_b, wv_b,
        Qhi, Qlo, Khi, Klo, Vhi, Vlo, nullptr,
        MTOT, DMODEL, DMODEL, 1);

    dim3 agrid(SEQ / 128, NH, BATCH);
    mma_attn_kernel<<<agrid, NT, ATTN_SMEM_B>>>(Qhi, Qlo, Khi, Klo, Vhi, Vlo, AOhi, AOlo);

    dim3 ggrid(DMODEL / 128, MTOT / 128, 1);
    mma_gemm_kernel<<<ggrid, NT, GEMM_SMEM_B>>>(
        AOhi, AOlo, whi + 3 * WW, wlo + 3 * WW, wo_b, nullptr, nullptr,
        nullptr, nullptr, nullptr, nullptr, nullptr, nullptr, out,
        MTOT, DMODEL, DMODEL, 0);
}

// round 12
// speedup vs baseline: 1.0670x; 1.0670x over previous
#include <cuda_runtime.h>
#include <cuda_bf16.h>
#include <cstdint>
#include <cstddef>

// Problem constants
#define BATCH   2
#define SEQ     2048
#define DMODEL  1024
#define NH      16
#define DH      64
#define MTOT    (BATCH * SEQ)        // 4096 rows

// ---------------------------------------------------------------------------
// Scratch (device globals; no allocations allowed)
// ---------------------------------------------------------------------------
__device__ __nv_bfloat16 g_xhi [MTOT * DMODEL];
__device__ __nv_bfloat16 g_xlo [MTOT * DMODEL];
__device__ __nv_bfloat16 g_whi [4][DMODEL * DMODEL];
__device__ __nv_bfloat16 g_wlo [4][DMODEL * DMODEL];
__device__ __nv_bfloat16 g_Qhi [MTOT * DMODEL];
__device__ __nv_bfloat16 g_Qlo [MTOT * DMODEL];
__device__ __nv_bfloat16 g_Khi [MTOT * DMODEL];
__device__ __nv_bfloat16 g_Klo [MTOT * DMODEL];
__device__ __nv_bfloat16 g_Vhi [MTOT * DMODEL];
__device__ __nv_bfloat16 g_Vlo [MTOT * DMODEL];
__device__ __nv_bfloat16 g_AOhi[MTOT * DMODEL];
__device__ __nv_bfloat16 g_AOlo[MTOT * DMODEL];

// ---------------------------------------------------------------------------
// Helpers
// ---------------------------------------------------------------------------
__device__ __forceinline__ void mma_bf16(float* c, const uint32_t* a, const uint32_t* b) {
    asm volatile(
        "mma.sync.aligned.m16n8k16.row.col.f32.bf16.bf16.f32 "
        "{%0,%1,%2,%3}, {%4,%5,%6,%7}, {%8,%9}, {%0,%1,%2,%3};"
        : "+f"(c[0]), "+f"(c[1]), "+f"(c[2]), "+f"(c[3])
        : "r"(a[0]), "r"(a[1]), "r"(a[2]), "r"(a[3]),
          "r"(b[0]), "r"(b[1]));
}

__device__ __forceinline__ uint32_t pack2_bf16(float a, float b) {
    __nv_bfloat162 t = __floats2bfloat162_rn(a, b);
    return *(uint32_t*)&t;
}
__device__ __forceinline__ float bf16_hi(float x) {
    return __bfloat162float(__float2bfloat16(x));
}

__device__ __forceinline__ uint32_t smem_u32(const void* p) {
    uint32_t a;
    asm("{ .reg .u64 t; cvta.to.shared.u64 t, %1; cvt.u32.u64 %0, t; }"
        : "=r"(a) : "l"(p));
    return a;
}

__device__ __forceinline__ void cp16(uint32_t dst, const void* src) {
    asm volatile("cp.async.cg.shared.global [%0], [%1], 16;" :: "r"(dst), "l"(src));
}
#define CP_COMMIT() asm volatile("cp.async.commit_group;" ::: "memory")
#define CP_WAIT(n)  asm volatile("cp.async.wait_group %0;" :: "n"(n) : "memory")

__device__ __forceinline__ void ldsm_x4(uint32_t* r, uint32_t addr) {
    asm volatile("ldmatrix.sync.aligned.m8n8.x4.shared.b16 {%0,%1,%2,%3}, [%4];"
        : "=r"(r[0]), "=r"(r[1]), "=r"(r[2]), "=r"(r[3]) : "r"(addr));
}
__device__ __forceinline__ void ldsm_x4_t(uint32_t* r, uint32_t addr) {
    asm volatile("ldmatrix.sync.aligned.m8n8.x4.trans.shared.b16 {%0,%1,%2,%3}, [%4];"
        : "=r"(r[0]), "=r"(r[1]), "=r"(r[2]), "=r"(r[3]) : "r"(addr));
}

// ---------------------------------------------------------------------------
// Split kernel: fp32 -> bf16 hi + bf16 lo residual
// ---------------------------------------------------------------------------
__global__ void split_kernel(const float* __restrict__ src,
                             __nv_bfloat16* __restrict__ hi,
                             __nv_bfloat16* __restrict__ lo, int n4)
{
    int i = blockIdx.x * blockDim.x + threadIdx.x;
    if (i >= n4) return;
    float4 v = ((const float4*)src)[i];
    uint2 h, l;
    h.x = pack2_bf16(v.x, v.y);
    h.y = pack2_bf16(v.z, v.w);
    l.x = pack2_bf16(v.x - bf16_hi(v.x), v.y - bf16_hi(v.y));
    l.y = pack2_bf16(v.z - bf16_hi(v.z), v.w - bf16_hi(v.w));
    ((uint2*)hi)[i] = h;
    ((uint2*)lo)[i] = l;
}

// ===========================================================================
// Split-bf16 GEMM: CTA tile 256(M)x128(N), BK=64, 256 threads / 8 warps
// (4M x 2N, warp tile 64x64 -> 83 B crossbar per MMA). 2-stage cp.async ring.
// ===========================================================================
#define GS 72
#define GT  (128 * GS)                 // 128-row tile (halves)
#define GTA (256 * GS)                 // 256-row tile (halves)
#define GSTG (2 * GTA + 2 * GT)        // one GEMM stage: Ahi Alo Bhi Blo
#define GEMM_SMEM_B (2 * GSTG * 2)     // 221184 B

__global__ __launch_bounds__(256, 1)
void mma_gemm_kernel(const __nv_bfloat16* __restrict__ Ah,
                     const __nv_bfloat16* __restrict__ Al,
                     const __nv_bfloat16* __restrict__ Wh,
                     const __nv_bfloat16* __restrict__ Wl,
                     const float* __restrict__ b0,
                     const float* __restrict__ b1,
                     const float* __restrict__ b2,
                     __nv_bfloat16* __restrict__ C0h, __nv_bfloat16* __restrict__ C0l,
                     __nv_bfloat16* __restrict__ C1h, __nv_bfloat16* __restrict__ C1l,
                     __nv_bfloat16* __restrict__ C2h, __nv_bfloat16* __restrict__ C2l,
                     float* __restrict__ Cf,
                     int M, int N, int K, int mode)
{
    extern __shared__ __nv_bfloat16 sm[];
    const uint32_t sb = smem_u32(sm);

    const int z = blockIdx.z;
    const __nv_bfloat16* Bh = Wh + (size_t)z * DMODEL * DMODEL;
    const __nv_bfloat16* Bl = Wl + (size_t)z * DMODEL * DMODEL;
    const float* bias = (z == 0) ? b0 : (z == 1) ? b1 : b2;
    __nv_bfloat16* Chi = (z == 0) ? C0h : (z == 1) ? C1h : C2h;
    __nv_bfloat16* Clo = (z == 0) ? C0l : (z == 1) ? C1l : C2l;

    const int t    = threadIdx.x;
    const int wid  = t >> 5;
    const int lane = t & 31;
    const int g    = lane >> 2;
    const int tq   = lane & 3;
    const int q    = lane >> 3;
    const int l8   = lane & 7;
    const int m0   = (wid >> 1) * 64;   // 4 M-warps x 64 rows
    const int n0   = (wid & 1) * 64;    // 2 N-warps x 64 cols

    const int bm = blockIdx.y * 256;
    const int bn = blockIdx.x * 128;

    float acc[4][8][4];
#pragma unroll
    for (int mi = 0; mi < 4; mi++)
#pragma unroll
        for (int ni = 0; ni < 8; ni++)
#pragma unroll
            for (int e = 0; e < 4; e++) acc[mi][ni][e] = 0.0f;

    const int NCHUNK = K / 64;    // 16

    auto fill = [&](int c, int s) {
        const int k0 = c * 64;
        const uint32_t SA = s * GSTG;
        const uint32_t SB_ = SA + 2 * GTA;
        // A: 256 rows x 8 segs
#pragma unroll
        for (int i = 0; i < 8; i++) {
            const int l   = i * 256 + t;
            const int row = l >> 3;
            const int seg = l & 7;
            const uint32_t d = sb + 2 * (SA + row * GS + seg * 8);
            const size_t   o = (size_t)(bm + row) * K + k0 + seg * 8;
            cp16(d,           Ah + o);
            cp16(d + 2 * GTA, Al + o);
        }
        // B: 128 rows x 8 segs
#pragma unroll
        for (int i = 0; i < 4; i++) {
            const int l   = i * 256 + t;
            const int row = l >> 3;
            const int seg = l & 7;
            const uint32_t d = sb + 2 * (SB_ + row * GS + seg * 8);
            const size_t   o = (size_t)(bn + row) * K + k0 + seg * 8;
            cp16(d,          Bh + o);
            cp16(d + 2 * GT, Bl + o);
        }
    };

    fill(0, 0); CP_COMMIT();
    fill(1, 1); CP_COMMIT();

    for (int c = 0; c < NCHUNK; c++) {
        if (c == NCHUNK - 1) { CP_WAIT(0); } else { CP_WAIT(1); }
        __syncthreads();

        const uint32_t SA   = (c & 1) * GSTG;
        const uint32_t sAhi = sb + 2 * SA;
        const uint32_t sAlo = sAhi + 2 * GTA;
        const uint32_t sBhi = sAlo + 2 * GTA;
        const uint32_t sBlo = sBhi + 2 * GT;

#pragma unroll
        for (int ks = 0; ks < 4; ks++) {
            const int kk = ks * 16;

            uint32_t ah[4][4], al[4][4];
#pragma unroll
            for (int mi = 0; mi < 4; mi++) {
                const int arow = m0 + mi * 16 + (q & 1) * 8 + l8;
                const int acol = kk + (q >> 1) * 8;
                ldsm_x4(ah[mi], sAhi + 2 * (arow * GS + acol));
                ldsm_x4(al[mi], sAlo + 2 * (arow * GS + acol));
            }
#pragma unroll
            for (int p = 0; p < 2; p++) {
                uint32_t bh[2][4], bl[2][4];
#pragma unroll
                for (int j = 0; j < 2; j++) {
                    const int brow = n0 + (2 * p + j) * 16 + (q >> 1) * 8 + l8;
                    const int bcol = kk + (q & 1) * 8;
                    ldsm_x4(bh[j], sBhi + 2 * (brow * GS + bcol));
                    ldsm_x4(bl[j], sBlo + 2 * (brow * GS + bcol));
                }
                // pass hh (16 independent)
#pragma unroll
                for (int mi = 0; mi < 4; mi++)
#pragma unroll
                    for (int j = 0; j < 2; j++) {
                        const int ni = (2 * p + j) * 2;
                        mma_bf16(acc[mi][ni],     ah[mi], bh[j]);
                        mma_bf16(acc[mi][ni + 1], ah[mi], bh[j] + 2);
                    }
                // pass hl
#pragma unroll
                for (int mi = 0; mi < 4; mi++)
#pragma unroll
                    for (int j = 0; j < 2; j++) {
                        const int ni = (2 * p + j) * 2;
                        mma_bf16(acc[mi][ni],     ah[mi], bl[j]);
                        mma_bf16(acc[mi][ni + 1], ah[mi], bl[j] + 2);
                    }
                // pass lh
#pragma unroll
                for (int mi = 0; mi < 4; mi++)
#pragma unroll
                    for (int j = 0; j < 2; j++) {
                        const int ni = (2 * p + j) * 2;
                        mma_bf16(acc[mi][ni],     al[mi], bh[j]);
                        mma_bf16(acc[mi][ni + 1], al[mi], bh[j] + 2);
                    }
            }
        }
        __syncthreads();
        if (c + 2 < NCHUNK) { fill(c + 2, c & 1); CP_COMMIT(); }
    }

    // Epilogue
#pragma unroll
    for (int mi = 0; mi < 4; mi++) {
        const int r0 = bm + m0 + mi * 16 + g;
#pragma unroll
        for (int ni = 0; ni < 8; ni++) {
            const int col = bn + n0 + ni * 8 + 2 * tq;
            const float bb0 = bias[col], bb1 = bias[col + 1];
            float c00 = acc[mi][ni][0] + bb0, c01 = acc[mi][ni][1] + bb1;
            float c10 = acc[mi][ni][2] + bb0, c11 = acc[mi][ni][3] + bb1;
            if (mode == 0) {
                float2 v0 = {c00, c01}, v1 = {c10, c11};
                *(float2*)&Cf[(size_t)r0 * N + col]       = v0;
                *(float2*)&Cf[(size_t)(r0 + 8) * N + col] = v1;
            } else {
                *(uint32_t*)&Chi[(size_t)r0 * N + col] = pack2_bf16(c00, c01);
                *(uint32_t*)&Clo[(size_t)r0 * N + col] =
                    pack2_bf16(c00 - bf16_hi(c00), c01 - bf16_hi(c01));
                *(uint32_t*)&Chi[(size_t)(r0 + 8) * N + col] = pack2_bf16(c10, c11);
                *(uint32_t*)&Clo[(size_t)(r0 + 8) * N + col] =
                    pack2_bf16(c10 - bf16_hi(c10), c11 - bf16_hi(c11));
            }
        }
    }
}

// ===========================================================================
// FA2-style split-bf16 causal attention: 256 threads / 8 warps as
// 4 q-groups (32 rows) x 2 n-halves (64 cols). S and O register-resident;
// Q in dedicated smem tiles; 2-stage K/V ring; O pair-reduction via smem.
// smem: Qhi@0 Qlo@GT; stage s: Khi@(2+4s) Klo@(3+4s) Vhi@(4+4s) Vlo@(5+4s).
// ===========================================================================
#define ATTN_SMEM_B (10 * GT * 2)     // 184320 B

__global__ __launch_bounds__(256, 1)
void mma_attn_kernel(const __nv_bfloat16* __restrict__ Qh,
                     const __nv_bfloat16* __restrict__ Ql,
                     const __nv_bfloat16* __restrict__ Kh,
                     const __nv_bfloat16* __restrict__ Kl,
                     const __nv_bfloat16* __restrict__ Vh,
                     const __nv_bfloat16* __restrict__ Vl,
                     __nv_bfloat16* __restrict__ Ohi,
                     __nv_bfloat16* __restrict__ Olo)
{
    extern __shared__ __nv_bfloat16 sm[];
    const uint32_t sb = smem_u32(sm);

    const int qb = (gridDim.x - 1) - blockIdx.x;   // heavy CTAs first
    const int h  = blockIdx.y;
    const int b  = blockIdx.z;

    const int t    = threadIdx.x;
    const int wid  = t >> 5;
    const int lane = t & 31;
    const int g    = lane >> 2;
    const int tq   = lane & 3;
    const int q    = lane >> 3;
    const int l8   = lane & 7;
    const int qw   = wid & 3;           // q-row group 0..3 (32 rows each)
    const int nh   = wid >> 2;          // n-half 0/1
    const int m0   = qw * 32;
    const int nc0  = nh * 64;

    const int hoff  = h * DH;
    const int brow0 = b * SEQ;
    const int qrow0 = brow0 + qb * 128;

    auto fillKV = [&](int kb, int s) {
        const int krow0 = brow0 + kb * 128;
        const uint32_t SK = (2 + 4 * s) * GT;
        const uint32_t SV = (4 + 4 * s) * GT;
#pragma unroll
        for (int i = 0; i < 4; i++) {
            const int l   = i * 256 + t;
            const int row = l >> 3;
            const int seg = l & 7;
            const uint32_t off = row * GS + seg * 8;
            const size_t   sidx = (size_t)(krow0 + row) * DMODEL + hoff + seg * 8;
            cp16(sb + 2 * (SK + off),      Kh + sidx);
            cp16(sb + 2 * (SK + GT + off), Kl + sidx);
            cp16(sb + 2 * (SV + off),      Vh + sidx);
            cp16(sb + 2 * (SV + GT + off), Vl + sidx);
        }
    };

    // ---- prologue: Q + KV stage 0; KV stage 1 ----
#pragma unroll
    for (int i = 0; i < 4; i++) {
        const int l   = i * 256 + t;
        const int row = l >> 3;
        const int seg = l & 7;
        const uint32_t d = sb + 2 * (row * GS + seg * 8);
        const size_t   o = (size_t)(qrow0 + row) * DMODEL + hoff + seg * 8;
        cp16(d,          Qh + o);
        cp16(d + 2 * GT, Ql + o);
    }
    fillKV(0, 0);
    CP_COMMIT();
    if (qb >= 1) { fillKV(1, 1); CP_COMMIT(); }

    float o[2][8][4];
#pragma unroll
    for (int mi = 0; mi < 2; mi++)
#pragma unroll
        for (int ni = 0; ni < 8; ni++)
#pragma unroll
            for (int e = 0; e < 4; e++) o[mi][ni][e] = 0.0f;

    for (int kb = 0; kb <= qb; kb++) {
        if (kb == qb) { CP_WAIT(0); } else { CP_WAIT(1); }
        __syncthreads();

        const uint32_t SK   = (2 + 4 * (kb & 1)) * GT;
        const uint32_t SV   = (4 + 4 * (kb & 1)) * GT;
        const uint32_t sKhi = sb + 2 * SK;
        const uint32_t sKlo = sKhi + 2 * GT;
        const uint32_t sVhi = sb + 2 * SV;
        const uint32_t sVlo = sVhi + 2 * GT;

        // ---- Phase 1: S[32 x 64] (this warp's n-half) ----
        float s[2][8][4];
#pragma unroll
        for (int mi = 0; mi < 2; mi++)
#pragma unroll
            for (int nt = 0; nt < 8; nt++)
#pragma unroll
                for (int e = 0; e < 4; e++) s[mi][nt][e] = 0.0f;

#pragma unroll
        for (int ks = 0; ks < 4; ks++) {
            const int kk = ks * 16;
            uint32_t qhf[2][4], qlf[2][4];
#pragma unroll
            for (int mi = 0; mi < 2; mi++) {
                const int arow = m0 + mi * 16 + (q & 1) * 8 + l8;
                const int acol = kk + (q >> 1) * 8;
                ldsm_x4(qhf[mi], sb + 2 * (arow * GS + acol));
                ldsm_x4(qlf[mi], sb + 2 * (GT + arow * GS + acol));
            }
            uint32_t bh[4][4], bl[4][4];
#pragma unroll
            for (int j = 0; j < 4; j++) {
                const int brow = nc0 + j * 16 + (q >> 1) * 8 + l8;
                const int bcol = kk + (q & 1) * 8;
                ldsm_x4(bh[j], sKhi + 2 * (brow * GS + bcol));
                ldsm_x4(bl[j], sKlo + 2 * (brow * GS + bcol));
            }
            // pass hh (16 independent)
#pragma unroll
            for (int mi = 0; mi < 2; mi++)
#pragma unroll
                for (int j = 0; j < 4; j++) {
                    mma_bf16(s[mi][2 * j],     qhf[mi], bh[j]);
                    mma_bf16(s[mi][2 * j + 1], qhf[mi], bh[j] + 2);
                }
            // pass hl
#pragma unroll
            for (int mi = 0; mi < 2; mi++)
#pragma unroll
                for (int j = 0; j < 4; j++) {
                    mma_bf16(s[mi][2 * j],     qhf[mi], bl[j]);
                    mma_bf16(s[mi][2 * j + 1], qhf[mi], bl[j] + 2);
                }
            // pass lh
#pragma unroll
            for (int mi = 0; mi < 2; mi++)
#pragma unroll
                for (int j = 0; j < 4; j++) {
                    mma_bf16(s[mi][2 * j],     qlf[mi], bh[j]);
                    mma_bf16(s[mi][2 * j + 1], qlf[mi], bh[j] + 2);
                }
        }

        // Diagonal-block causal mask: keep col <= row
        if (kb == qb) {
#pragma unroll
            for (int mi = 0; mi < 2; mi++) {
                const int r0 = m0 + mi * 16 + g, r1 = r0 + 8;
#pragma unroll
                for (int nt = 0; nt < 8; nt++) {
                    const int c0 = nc0 + nt * 8 + 2 * tq;
                    if (c0     > r0) s[mi][nt][0] = 0.0f;
                    if (c0 + 1 > r0) s[mi][nt][1] = 0.0f;
                    if (c0     > r1) s[mi][nt][2] = 0.0f;
                    if (c0 + 1 > r1) s[mi][nt][3] = 0.0f;
                }
            }
        }

        // ---- Phase 2: O[32 x 64] += S(n-half) @ V(n-half rows, all 64 d) ----
#pragma unroll
        for (int kc = 0; kc < 4; kc++) {
            uint32_t ah[2][4], al[2][4];
#pragma unroll
            for (int mi = 0; mi < 2; mi++) {
                const float v0 = s[mi][2 * kc][0],     v1 = s[mi][2 * kc][1];
                const float v2 = s[mi][2 * kc][2],     v3 = s[mi][2 * kc][3];
                const float w0 = s[mi][2 * kc + 1][0], w1 = s[mi][2 * kc + 1][1];
                const float w2 = s[mi][2 * kc + 1][2], w3 = s[mi][2 * kc + 1][3];
                ah[mi][0] = pack2_bf16(v0, v1);
                ah[mi][1] = pack2_bf16(v2, v3);
                ah[mi][2] = pack2_bf16(w0, w1);
                ah[mi][3] = pack2_bf16(w2, w3);
                al[mi][0] = pack2_bf16(v0 - bf16_hi(v0), v1 - bf16_hi(v1));
                al[mi][1] = pack2_bf16(v2 - bf16_hi(v2), v3 - bf16_hi(v3));
                al[mi][2] = pack2_bf16(w0 - bf16_hi(w0), w1 - bf16_hi(w1));
                al[mi][3] = pack2_bf16(w2 - bf16_hi(w2), w3 - bf16_hi(w3));
            }
            const int vr = nc0 + kc * 16 + (q & 1) * 8 + l8;
            uint32_t bh[4][4], bl[4][4];
#pragma unroll
            for (int dg = 0; dg < 4; dg++) {
                const int vcol = dg * 16 + (q >> 1) * 8;
                ldsm_x4_t(bh[dg], sVhi + 2 * (vr * GS + vcol));
                ldsm_x4_t(bl[dg], sVlo + 2 * (vr * GS + vcol));
            }
            // pass hh (16 independent)
#pragma unroll
            for (int mi = 0; mi < 2; mi++)
#pragma unroll
                for (int dg = 0; dg < 4; dg++) {
                    mma_bf16(o[mi][2 * dg],     ah[mi], bh[dg]);
                    mma_bf16(o[mi][2 * dg + 1], ah[mi], bh[dg] + 2);
                }
            // pass hl
#pragma unroll
            for (int mi = 0; mi < 2; mi++)
#pragma unroll
                for (int dg = 0; dg < 4; dg++) {
                    mma_bf16(o[mi][2 * dg],     ah[mi], bl[dg]);
                    mma_bf16(o[mi][2 * dg + 1], ah[mi], bl[dg] + 2);
                }
            // pass lh
#pragma unroll
            for (int mi = 0; mi < 2; mi++)
#pragma unroll
                for (int dg = 0; dg < 4; dg++) {
                    mma_bf16(o[mi][2 * dg],     al[mi], bh[dg]);
                    mma_bf16(o[mi][2 * dg + 1], al[mi], bh[dg] + 2);
                }
        }

        __syncthreads();
        if (kb + 2 <= qb) { fillKV(kb + 2, kb & 1); CP_COMMIT(); }
    }

    // ---- Reduce O partials across n-half warp pairs (overlay Q tiles+) ----
    __syncthreads();
    float* red = (float*)sm;              // 128 rows x 64 cols fp32 = 32KB
    if (nh == 1) {
#pragma unroll
        for (int mi = 0; mi < 2; mi++)
#pragma unroll
            for (int ni = 0; ni < 8; ni++) {
                const int col = ni * 8 + 2 * tq;
                const int row = m0 + mi * 16 + g;
                float2 v0 = {o[mi][ni][0], o[mi][ni][1]};
                float2 v1 = {o[mi][ni][2], o[mi][ni][3]};
                *(float2*)&red[row * 64 + col]       = v0;
                *(float2*)&red[(row + 8) * 64 + col] = v1;
            }
    }
    __syncthreads();

    if (nh == 0) {
#pragma unroll
        for (int mi = 0; mi < 2; mi++)
#pragma unroll
            for (int ni = 0; ni < 8; ni++) {
                const int col = ni * 8 + 2 * tq;
                const int row = m0 + mi * 16 + g;
                float2 v0 = *(const float2*)&red[row * 64 + col];
                float2 v1 = *(const float2*)&red[(row + 8) * 64 + col];
                const float c00 = o[mi][ni][0] + v0.x, c01 = o[mi][ni][1] + v0.y;
                const float c10 = o[mi][ni][2] + v1.x, c11 = o[mi][ni][3] + v1.y;
                const int gc = hoff + col;
                const size_t r0 = (size_t)(qrow0 + row) * DMODEL + gc;
                const size_t r1 = (size_t)(qrow0 + row + 8) * DMODEL + gc;
                *(uint32_t*)&Ohi[r0] = pack2_bf16(c00, c01);
                *(uint32_t*)&Olo[r0] = pack2_bf16(c00 - bf16_hi(c00), c01 - bf16_hi(c01));
                *(uint32_t*)&Ohi[r1] = pack2_bf16(c10, c11);
                *(uint32_t*)&Olo[r1] = pack2_bf16(c10 - bf16_hi(c10), c11 - bf16_hi(c11));
            }
    }
}

// ---------------------------------------------------------------------------
// Launch
// ---------------------------------------------------------------------------
extern "C" void kernel_launch(void* const* d_in, const int* in_sizes, int n_in,
                              void* d_out, int out_size)
{
    const float* x    = (const float*)d_in[0];
    const float* wq_w = (const float*)d_in[1];
    const float* wq_b = (const float*)d_in[2];
    const float* wk_w = (const float*)d_in[3];
    const float* wk_b = (const float*)d_in[4];
    const float* wv_w = (const float*)d_in[5];
    const float* wv_b = (const float*)d_in[6];
    const float* wo_w = (const float*)d_in[7];
    const float* wo_b = (const float*)d_in[8];
    float* out = (float*)d_out;

    __nv_bfloat16 *xhi, *xlo, *whi, *wlo;
    __nv_bfloat16 *Qhi, *Qlo, *Khi, *Klo, *Vhi, *Vlo, *AOhi, *AOlo;
    cudaGetSymbolAddress((void**)&xhi,  g_xhi);
    cudaGetSymbolAddress((void**)&xlo,  g_xlo);
    cudaGetSymbolAddress((void**)&whi,  g_whi);
    cudaGetSymbolAddress((void**)&wlo,  g_wlo);
    cudaGetSymbolAddress((void**)&Qhi,  g_Qhi);
    cudaGetSymbolAddress((void**)&Qlo,  g_Qlo);
    cudaGetSymbolAddress((void**)&Khi,  g_Khi);
    cudaGetSymbolAddress((void**)&Klo,  g_Klo);
    cudaGetSymbolAddress((void**)&Vhi,  g_Vhi);
    cudaGetSymbolAddress((void**)&Vlo,  g_Vlo);
    cudaGetSymbolAddress((void**)&AOhi, g_AOhi);
    cudaGetSymbolAddress((void**)&AOlo, g_AOlo);

    cudaFuncSetAttribute(mma_gemm_kernel,
                         cudaFuncAttributeMaxDynamicSharedMemorySize, GEMM_SMEM_B);
    cudaFuncSetAttribute(mma_attn_kernel,
                         cudaFuncAttributeMaxDynamicSharedMemorySize, ATTN_SMEM_B);

    const size_t WW = (size_t)DMODEL * DMODEL;

    split_kernel<<<(MTOT * DMODEL / 4 + 255) / 256, 256>>>(x, xhi, xlo, MTOT * DMODEL / 4);
    split_kernel<<<((int)WW / 4 + 255) / 256, 256>>>(wq_w, whi + 0 * WW, wlo + 0 * WW, WW / 4);
    split_kernel<<<((int)WW / 4 + 255) / 256, 256>>>(wk_w, whi + 1 * WW, wlo + 1 * WW, WW / 4);
    split_kernel<<<((int)WW / 4 + 255) / 256, 256>>>(wv_w, whi + 2 * WW, wlo + 2 * WW, WW / 4);
    split_kernel<<<((int)WW / 4 + 255) / 256, 256>>>(wo_w, whi + 3 * WW, wlo + 3 * WW, WW / 4);

    // Fused Q/K/V projections: CTA tile 256x128
    dim3 gqkv(DMODEL / 128, MTOT / 256, 3);     // (8, 16, 3)
    mma_gemm_kernel<<<gqkv, 256, GEMM_SMEM_B>>>(
        xhi, xlo, whi, wlo, wq_b, wk_b, wv_b,
        Qhi, Qlo, Khi, Klo, Vhi, Vlo, nullptr,
        MTOT, DMODEL, DMODEL, 1);

    dim3 agrid(SEQ / 128, NH, BATCH);           // (16, 16, 2)
    mma_attn_kernel<<<agrid, 256, ATTN_SMEM_B>>>(Qhi, Qlo, Khi, Klo, Vhi, Vlo, AOhi, AOlo);

    dim3 ggrid(DMODEL / 128, MTOT / 256, 1);    // (8, 16, 1)
    mma_gemm_kernel<<<ggrid, 256, GEMM_SMEM_B>>>(
        AOhi, AOlo, whi + 3 * WW, wlo + 3 * WW, wo_b, nullptr, nullptr,
        nullptr, nullptr, nullptr, nullptr, nullptr, nullptr, out,
        MTOT, DMODEL, DMODEL, 0);
}

// round 13
// speedup vs baseline: 1.0815x; 1.0136x over previous
#include <cuda_runtime.h>
#include <cuda_bf16.h>
#include <cstdint>
#include <cstddef>

// Problem constants
#define BATCH   2
#define SEQ     2048
#define DMODEL  1024
#define NH      16
#define DH      64
#define MTOT    (BATCH * SEQ)        // 4096 rows

// ---------------------------------------------------------------------------
// Scratch (device globals; no allocations allowed)
// ---------------------------------------------------------------------------
__device__ __nv_bfloat16 g_xhi [MTOT * DMODEL];
__device__ __nv_bfloat16 g_xlo [MTOT * DMODEL];
__device__ __nv_bfloat16 g_whi [4][DMODEL * DMODEL];
__device__ __nv_bfloat16 g_wlo [4][DMODEL * DMODEL];
__device__ __nv_bfloat16 g_Qhi [MTOT * DMODEL];
__device__ __nv_bfloat16 g_Qlo [MTOT * DMODEL];
__device__ __nv_bfloat16 g_Khi [MTOT * DMODEL];
__device__ __nv_bfloat16 g_Klo [MTOT * DMODEL];
__device__ __nv_bfloat16 g_Vhi [MTOT * DMODEL];
__device__ __nv_bfloat16 g_Vlo [MTOT * DMODEL];
__device__ __nv_bfloat16 g_AOhi[MTOT * DMODEL];
__device__ __nv_bfloat16 g_AOlo[MTOT * DMODEL];

// ---------------------------------------------------------------------------
// Helpers
// ---------------------------------------------------------------------------
__device__ __forceinline__ void mma_bf16(float* c, const uint32_t* a, const uint32_t* b) {
    asm volatile(
        "mma.sync.aligned.m16n8k16.row.col.f32.bf16.bf16.f32 "
        "{%0,%1,%2,%3}, {%4,%5,%6,%7}, {%8,%9}, {%0,%1,%2,%3};"
        : "+f"(c[0]), "+f"(c[1]), "+f"(c[2]), "+f"(c[3])
        : "r"(a[0]), "r"(a[1]), "r"(a[2]), "r"(a[3]),
          "r"(b[0]), "r"(b[1]));
}

__device__ __forceinline__ uint32_t pack2_bf16(float a, float b) {
    __nv_bfloat162 t = __floats2bfloat162_rn(a, b);
    return *(uint32_t*)&t;
}
__device__ __forceinline__ float bf16_hi(float x) {
    return __bfloat162float(__float2bfloat16(x));
}

__device__ __forceinline__ uint32_t smem_u32(const void* p) {
    uint32_t a;
    asm("{ .reg .u64 t; cvta.to.shared.u64 t, %1; cvt.u32.u64 %0, t; }"
        : "=r"(a) : "l"(p));
    return a;
}

__device__ __forceinline__ void cp16(uint32_t dst, const void* src) {
    asm volatile("cp.async.cg.shared.global [%0], [%1], 16;" :: "r"(dst), "l"(src));
}
#define CP_COMMIT() asm volatile("cp.async.commit_group;" ::: "memory")
#define CP_WAIT(n)  asm volatile("cp.async.wait_group %0;" :: "n"(n) : "memory")

__device__ __forceinline__ void ldsm_x4(uint32_t* r, uint32_t addr) {
    asm volatile("ldmatrix.sync.aligned.m8n8.x4.shared.b16 {%0,%1,%2,%3}, [%4];"
        : "=r"(r[0]), "=r"(r[1]), "=r"(r[2]), "=r"(r[3]) : "r"(addr));
}
__device__ __forceinline__ void ldsm_x4_t(uint32_t* r, uint32_t addr) {
    asm volatile("ldmatrix.sync.aligned.m8n8.x4.trans.shared.b16 {%0,%1,%2,%3}, [%4];"
        : "=r"(r[0]), "=r"(r[1]), "=r"(r[2]), "=r"(r[3]) : "r"(addr));
}

// ---------------------------------------------------------------------------
// Split kernels: fp32 -> bf16 hi + bf16 lo residual
// ---------------------------------------------------------------------------
__global__ void split_kernel(const float* __restrict__ src,
                             __nv_bfloat16* __restrict__ hi,
                             __nv_bfloat16* __restrict__ lo, int n4)
{
    int i = blockIdx.x * blockDim.x + threadIdx.x;
    if (i >= n4) return;
    float4 v = ((const float4*)src)[i];
    uint2 h, l;
    h.x = pack2_bf16(v.x, v.y);
    h.y = pack2_bf16(v.z, v.w);
    l.x = pack2_bf16(v.x - bf16_hi(v.x), v.y - bf16_hi(v.y));
    l.y = pack2_bf16(v.z - bf16_hi(v.z), v.w - bf16_hi(v.w));
    ((uint2*)hi)[i] = h;
    ((uint2*)lo)[i] = l;
}

// All 4 weights in one launch: blockIdx.y picks the weight.
__global__ void split4_kernel(const float* __restrict__ w0,
                              const float* __restrict__ w1,
                              const float* __restrict__ w2,
                              const float* __restrict__ w3,
                              __nv_bfloat16* __restrict__ hi,   // g_whi base
                              __nv_bfloat16* __restrict__ lo,   // g_wlo base
                              int n4)                            // per-weight float4 count
{
    const int z = blockIdx.y;
    const float* src = (z == 0) ? w0 : (z == 1) ? w1 : (z == 2) ? w2 : w3;
    int i = blockIdx.x * blockDim.x + threadIdx.x;
    if (i >= n4) return;
    float4 v = ((const float4*)src)[i];
    uint2 h, l;
    h.x = pack2_bf16(v.x, v.y);
    h.y = pack2_bf16(v.z, v.w);
    l.x = pack2_bf16(v.x - bf16_hi(v.x), v.y - bf16_hi(v.y));
    l.y = pack2_bf16(v.z - bf16_hi(v.z), v.w - bf16_hi(v.w));
    const size_t off = (size_t)z * ((size_t)DMODEL * DMODEL / 4);
    ((uint2*)hi)[off + i] = h;
    ((uint2*)lo)[off + i] = l;
}

// ===========================================================================
// Split-bf16 GEMM: CTA tile 256(M)x128(N), BK=64, 256 threads / 8 warps
// (4M x 2N, warp tile 64x64 -> 83 B crossbar per MMA). 2-stage cp.async ring.
// (unchanged from R12 — it delivered the win)
// ===========================================================================
#define GS 72
#define GT  (128 * GS)                 // 128-row tile (halves)
#define GTA (256 * GS)                 // 256-row tile (halves)
#define GSTG (2 * GTA + 2 * GT)        // one GEMM stage: Ahi Alo Bhi Blo
#define GEMM_SMEM_B (2 * GSTG * 2)     // 221184 B

__global__ __launch_bounds__(256, 1)
void mma_gemm_kernel(const __nv_bfloat16* __restrict__ Ah,
                     const __nv_bfloat16* __restrict__ Al,
                     const __nv_bfloat16* __restrict__ Wh,
                     const __nv_bfloat16* __restrict__ Wl,
                     const float* __restrict__ b0,
                     const float* __restrict__ b1,
                     const float* __restrict__ b2,
                     __nv_bfloat16* __restrict__ C0h, __nv_bfloat16* __restrict__ C0l,
                     __nv_bfloat16* __restrict__ C1h, __nv_bfloat16* __restrict__ C1l,
                     __nv_bfloat16* __restrict__ C2h, __nv_bfloat16* __restrict__ C2l,
                     float* __restrict__ Cf,
                     int M, int N, int K, int mode)
{
    extern __shared__ __nv_bfloat16 sm[];
    const uint32_t sb = smem_u32(sm);

    const int z = blockIdx.z;
    const __nv_bfloat16* Bh = Wh + (size_t)z * DMODEL * DMODEL;
    const __nv_bfloat16* Bl = Wl + (size_t)z * DMODEL * DMODEL;
    const float* bias = (z == 0) ? b0 : (z == 1) ? b1 : b2;
    __nv_bfloat16* Chi = (z == 0) ? C0h : (z == 1) ? C1h : C2h;
    __nv_bfloat16* Clo = (z == 0) ? C0l : (z == 1) ? C1l : C2l;

    const int t    = threadIdx.x;
    const int wid  = t >> 5;
    const int lane = t & 31;
    const int g    = lane >> 2;
    const int tq   = lane & 3;
    const int q    = lane >> 3;
    const int l8   = lane & 7;
    const int m0   = (wid >> 1) * 64;   // 4 M-warps x 64 rows
    const int n0   = (wid & 1) * 64;    // 2 N-warps x 64 cols

    const int bm = blockIdx.y * 256;
    const int bn = blockIdx.x * 128;

    float acc[4][8][4];
#pragma unroll
    for (int mi = 0; mi < 4; mi++)
#pragma unroll
        for (int ni = 0; ni < 8; ni++)
#pragma unroll
            for (int e = 0; e < 4; e++) acc[mi][ni][e] = 0.0f;

    const int NCHUNK = K / 64;    // 16

    auto fill = [&](int c, int s) {
        const int k0 = c * 64;
        const uint32_t SA = s * GSTG;
        const uint32_t SB_ = SA + 2 * GTA;
#pragma unroll
        for (int i = 0; i < 8; i++) {
            const int l   = i * 256 + t;
            const int row = l >> 3;
            const int seg = l & 7;
            const uint32_t d = sb + 2 * (SA + row * GS + seg * 8);
            const size_t   o = (size_t)(bm + row) * K + k0 + seg * 8;
            cp16(d,           Ah + o);
            cp16(d + 2 * GTA, Al + o);
        }
#pragma unroll
        for (int i = 0; i < 4; i++) {
            const int l   = i * 256 + t;
            const int row = l >> 3;
            const int seg = l & 7;
            const uint32_t d = sb + 2 * (SB_ + row * GS + seg * 8);
            const size_t   o = (size_t)(bn + row) * K + k0 + seg * 8;
            cp16(d,          Bh + o);
            cp16(d + 2 * GT, Bl + o);
        }
    };

    fill(0, 0); CP_COMMIT();
    fill(1, 1); CP_COMMIT();

    for (int c = 0; c < NCHUNK; c++) {
        if (c == NCHUNK - 1) { CP_WAIT(0); } else { CP_WAIT(1); }
        __syncthreads();

        const uint32_t SA   = (c & 1) * GSTG;
        const uint32_t sAhi = sb + 2 * SA;
        const uint32_t sAlo = sAhi + 2 * GTA;
        const uint32_t sBhi = sAlo + 2 * GTA;
        const uint32_t sBlo = sBhi + 2 * GT;

#pragma unroll
        for (int ks = 0; ks < 4; ks++) {
            const int kk = ks * 16;

            uint32_t ah[4][4], al[4][4];
#pragma unroll
            for (int mi = 0; mi < 4; mi++) {
                const int arow = m0 + mi * 16 + (q & 1) * 8 + l8;
                const int acol = kk + (q >> 1) * 8;
                ldsm_x4(ah[mi], sAhi + 2 * (arow * GS + acol));
                ldsm_x4(al[mi], sAlo + 2 * (arow * GS + acol));
            }
#pragma unroll
            for (int p = 0; p < 2; p++) {
                uint32_t bh[2][4], bl[2][4];
#pragma unroll
                for (int j = 0; j < 2; j++) {
                    const int brow = n0 + (2 * p + j) * 16 + (q >> 1) * 8 + l8;
                    const int bcol = kk + (q & 1) * 8;
                    ldsm_x4(bh[j], sBhi + 2 * (brow * GS + bcol));
                    ldsm_x4(bl[j], sBlo + 2 * (brow * GS + bcol));
                }
                // pass hh (16 independent)
#pragma unroll
                for (int mi = 0; mi < 4; mi++)
#pragma unroll
                    for (int j = 0; j < 2; j++) {
                        const int ni = (2 * p + j) * 2;
                        mma_bf16(acc[mi][ni],     ah[mi], bh[j]);
                        mma_bf16(acc[mi][ni + 1], ah[mi], bh[j] + 2);
                    }
                // pass hl
#pragma unroll
                for (int mi = 0; mi < 4; mi++)
#pragma unroll
                    for (int j = 0; j < 2; j++) {
                        const int ni = (2 * p + j) * 2;
                        mma_bf16(acc[mi][ni],     ah[mi], bl[j]);
                        mma_bf16(acc[mi][ni + 1], ah[mi], bl[j] + 2);
                    }
                // pass lh
#pragma unroll
                for (int mi = 0; mi < 4; mi++)
#pragma unroll
                    for (int j = 0; j < 2; j++) {
                        const int ni = (2 * p + j) * 2;
                        mma_bf16(acc[mi][ni],     al[mi], bh[j]);
                        mma_bf16(acc[mi][ni + 1], al[mi], bh[j] + 2);
                    }
            }
        }
        __syncthreads();
        if (c + 2 < NCHUNK) { fill(c + 2, c & 1); CP_COMMIT(); }
    }

    // Epilogue
#pragma unroll
    for (int mi = 0; mi < 4; mi++) {
        const int r0 = bm + m0 + mi * 16 + g;
#pragma unroll
        for (int ni = 0; ni < 8; ni++) {
            const int col = bn + n0 + ni * 8 + 2 * tq;
            const float bb0 = bias[col], bb1 = bias[col + 1];
            float c00 = acc[mi][ni][0] + bb0, c01 = acc[mi][ni][1] + bb1;
            float c10 = acc[mi][ni][2] + bb0, c11 = acc[mi][ni][3] + bb1;
            if (mode == 0) {
                float2 v0 = {c00, c01}, v1 = {c10, c11};
                *(float2*)&Cf[(size_t)r0 * N + col]       = v0;
                *(float2*)&Cf[(size_t)(r0 + 8) * N + col] = v1;
            } else {
                *(uint32_t*)&Chi[(size_t)r0 * N + col] = pack2_bf16(c00, c01);
                *(uint32_t*)&Clo[(size_t)r0 * N + col] =
                    pack2_bf16(c00 - bf16_hi(c00), c01 - bf16_hi(c01));
                *(uint32_t*)&Chi[(size_t)(r0 + 8) * N + col] = pack2_bf16(c10, c11);
                *(uint32_t*)&Clo[(size_t)(r0 + 8) * N + col] =
                    pack2_bf16(c10 - bf16_hi(c10), c11 - bf16_hi(c11));
            }
        }
    }
}

// ===========================================================================
// FA2-style split-bf16 causal attention: 256 threads / 8 warps as
// 4 q-groups (32 rows) x 2 n-halves (64 cols).
// R13: Q fragments register-resident across the whole kb loop;
//      fully-masked diagonal warp blocks skipped.
// smem: Qhi@0 Qlo@GT; stage s: K@(2+4s) V@(4+4s); 2-stage K/V ring.
// ===========================================================================
#define ATTN_SMEM_B (10 * GT * 2)     // 184320 B

__global__ __launch_bounds__(256, 1)
void mma_attn_kernel(const __nv_bfloat16* __restrict__ Qh,
                     const __nv_bfloat16* __restrict__ Ql,
                     const __nv_bfloat16* __restrict__ Kh,
                     const __nv_bfloat16* __restrict__ Kl,
                     const __nv_bfloat16* __restrict__ Vh,
                     const __nv_bfloat16* __restrict__ Vl,
                     __nv_bfloat16* __restrict__ Ohi,
                     __nv_bfloat16* __restrict__ Olo)
{
    extern __shared__ __nv_bfloat16 sm[];
    const uint32_t sb = smem_u32(sm);

    const int qb = (gridDim.x - 1) - blockIdx.x;   // heavy CTAs first
    const int h  = blockIdx.y;
    const int b  = blockIdx.z;

    const int t    = threadIdx.x;
    const int wid  = t >> 5;
    const int lane = t & 31;
    const int g    = lane >> 2;
    const int tq   = lane & 3;
    const int q    = lane >> 3;
    const int l8   = lane & 7;
    const int qw   = wid & 3;           // q-row group 0..3 (32 rows each)
    const int nh   = wid >> 2;          // n-half 0/1
    const int m0   = qw * 32;
    const int nc0  = nh * 64;
    const bool diag_skip = (nc0 >= m0 + 32);   // fully-masked diagonal block

    const int hoff  = h * DH;
    const int brow0 = b * SEQ;
    const int qrow0 = brow0 + qb * 128;

    auto fillKV = [&](int kb, int s) {
        const int krow0 = brow0 + kb * 128;
        const uint32_t SK = (2 + 4 * s) * GT;
        const uint32_t SV = (4 + 4 * s) * GT;
#pragma unroll
        for (int i = 0; i < 4; i++) {
            const int l   = i * 256 + t;
            const int row = l >> 3;
            const int seg = l & 7;
            const uint32_t off = row * GS + seg * 8;
            const size_t   sidx = (size_t)(krow0 + row) * DMODEL + hoff + seg * 8;
            cp16(sb + 2 * (SK + off),      Kh + sidx);
            cp16(sb + 2 * (SK + GT + off), Kl + sidx);
            cp16(sb + 2 * (SV + off),      Vh + sidx);
            cp16(sb + 2 * (SV + GT + off), Vl + sidx);
        }
    };

    // ---- prologue: Q + KV stage 0; KV stage 1 ----
#pragma unroll
    for (int i = 0; i < 4; i++) {
        const int l   = i * 256 + t;
        const int row = l >> 3;
        const int seg = l & 7;
        const uint32_t d = sb + 2 * (row * GS + seg * 8);
        const size_t   o = (size_t)(qrow0 + row) * DMODEL + hoff + seg * 8;
        cp16(d,          Qh + o);
        cp16(d + 2 * GT, Ql + o);
    }
    fillKV(0, 0);
    CP_COMMIT();
    if (qb >= 1) { fillKV(1, 1); CP_COMMIT(); }

    // Drain group 0 (Q + KV0), keep at most the KV1 prefetch in flight.
    if (qb >= 1) { CP_WAIT(1); } else { CP_WAIT(0); }
    __syncthreads();

    // ---- Q fragments register-resident for the whole kb loop ----
    uint32_t qfh[4][2][4], qfl[4][2][4];   // [ks][mi]
#pragma unroll
    for (int ks = 0; ks < 4; ks++)
#pragma unroll
        for (int mi = 0; mi < 2; mi++) {
            const int arow = m0 + mi * 16 + (q & 1) * 8 + l8;
            const int acol = ks * 16 + (q >> 1) * 8;
            ldsm_x4(qfh[ks][mi], sb + 2 * (arow * GS + acol));
            ldsm_x4(qfl[ks][mi], sb + 2 * (GT + arow * GS + acol));
        }

    float o[2][8][4];
#pragma unroll
    for (int mi = 0; mi < 2; mi++)
#pragma unroll
        for (int ni = 0; ni < 8; ni++)
#pragma unroll
            for (int e = 0; e < 4; e++) o[mi][ni][e] = 0.0f;

    for (int kb = 0; kb <= qb; kb++) {
        if (kb == qb) { CP_WAIT(0); } else { CP_WAIT(1); }
        __syncthreads();

        const bool active = !(kb == qb && diag_skip);

        if (active) {
            const uint32_t SK   = (2 + 4 * (kb & 1)) * GT;
            const uint32_t SV   = (4 + 4 * (kb & 1)) * GT;
            const uint32_t sKhi = sb + 2 * SK;
            const uint32_t sKlo = sKhi + 2 * GT;
            const uint32_t sVhi = sb + 2 * SV;
            const uint32_t sVlo = sVhi + 2 * GT;

            // ---- Phase 1: S[32 x 64] (this warp's n-half) ----
            float s[2][8][4];
#pragma unroll
            for (int mi = 0; mi < 2; mi++)
#pragma unroll
                for (int nt = 0; nt < 8; nt++)
#pragma unroll
                    for (int e = 0; e < 4; e++) s[mi][nt][e] = 0.0f;

#pragma unroll
            for (int ks = 0; ks < 4; ks++) {
                const int kk = ks * 16;
                uint32_t bh[4][4], bl[4][4];
#pragma unroll
                for (int j = 0; j < 4; j++) {
                    const int brow = nc0 + j * 16 + (q >> 1) * 8 + l8;
                    const int bcol = kk + (q & 1) * 8;
                    ldsm_x4(bh[j], sKhi + 2 * (brow * GS + bcol));
                    ldsm_x4(bl[j], sKlo + 2 * (brow * GS + bcol));
                }
                // pass hh (16 independent)
#pragma unroll
                for (int mi = 0; mi < 2; mi++)
#pragma unroll
                    for (int j = 0; j < 4; j++) {
                        mma_bf16(s[mi][2 * j],     qfh[ks][mi], bh[j]);
                        mma_bf16(s[mi][2 * j + 1], qfh[ks][mi], bh[j] + 2);
                    }
                // pass hl
#pragma unroll
                for (int mi = 0; mi < 2; mi++)
#pragma unroll
                    for (int j = 0; j < 4; j++) {
                        mma_bf16(s[mi][2 * j],     qfh[ks][mi], bl[j]);
                        mma_bf16(s[mi][2 * j + 1], qfh[ks][mi], bl[j] + 2);
                    }
                // pass lh
#pragma unroll
                for (int mi = 0; mi < 2; mi++)
#pragma unroll
                    for (int j = 0; j < 4; j++) {
                        mma_bf16(s[mi][2 * j],     qfl[ks][mi], bh[j]);
                        mma_bf16(s[mi][2 * j + 1], qfl[ks][mi], bh[j] + 2);
                    }
            }

            // Diagonal-block causal mask: keep col <= row
            if (kb == qb) {
#pragma unroll
                for (int mi = 0; mi < 2; mi++) {
                    const int r0 = m0 + mi * 16 + g, r1 = r0 + 8;
#pragma unroll
                    for (int nt = 0; nt < 8; nt++) {
                        const int c0 = nc0 + nt * 8 + 2 * tq;
                        if (c0     > r0) s[mi][nt][0] = 0.0f;
                        if (c0 + 1 > r0) s[mi][nt][1] = 0.0f;
                        if (c0     > r1) s[mi][nt][2] = 0.0f;
                        if (c0 + 1 > r1) s[mi][nt][3] = 0.0f;
                    }
                }
            }

            // ---- Phase 2: O[32 x 64] += S(n-half) @ V(n-half rows) ----
#pragma unroll
            for (int kc = 0; kc < 4; kc++) {
                uint32_t ah[2][4], al[2][4];
#pragma unroll
                for (int mi = 0; mi < 2; mi++) {
                    const float v0 = s[mi][2 * kc][0],     v1 = s[mi][2 * kc][1];
                    const float v2 = s[mi][2 * kc][2],     v3 = s[mi][2 * kc][3];
                    const float w0 = s[mi][2 * kc + 1][0], w1 = s[mi][2 * kc + 1][1];
                    const float w2 = s[mi][2 * kc + 1][2], w3 = s[mi][2 * kc + 1][3];
                    ah[mi][0] = pack2_bf16(v0, v1);
                    ah[mi][1] = pack2_bf16(v2, v3);
                    ah[mi][2] = pack2_bf16(w0, w1);
                    ah[mi][3] = pack2_bf16(w2, w3);
                    al[mi][0] = pack2_bf16(v0 - bf16_hi(v0), v1 - bf16_hi(v1));
                    al[mi][1] = pack2_bf16(v2 - bf16_hi(v2), v3 - bf16_hi(v3));
                    al[mi][2] = pack2_bf16(w0 - bf16_hi(w0), w1 - bf16_hi(w1));
                    al[mi][3] = pack2_bf16(w2 - bf16_hi(w2), w3 - bf16_hi(w3));
                }
                const int vr = nc0 + kc * 16 + (q & 1) * 8 + l8;
                uint32_t bh[4][4], bl[4][4];
#pragma unroll
                for (int dg = 0; dg < 4; dg++) {
                    const int vcol = dg * 16 + (q >> 1) * 8;
                    ldsm_x4_t(bh[dg], sVhi + 2 * (vr * GS + vcol));
                    ldsm_x4_t(bl[dg], sVlo + 2 * (vr * GS + vcol));
                }
                // pass hh (16 independent)
#pragma unroll
                for (int mi = 0; mi < 2; mi++)
#pragma unroll
                    for (int dg = 0; dg < 4; dg++) {
                        mma_bf16(o[mi][2 * dg],     ah[mi], bh[dg]);
                        mma_bf16(o[mi][2 * dg + 1], ah[mi], bh[dg] + 2);
                    }
                // pass hl
#pragma unroll
                for (int mi = 0; mi < 2; mi++)
#pragma unroll
                    for (int dg = 0; dg < 4; dg++) {
                        mma_bf16(o[mi][2 * dg],     ah[mi], bl[dg]);
                        mma_bf16(o[mi][2 * dg + 1], ah[mi], bl[dg] + 2);
                    }
                // pass lh
#pragma unroll
                for (int mi = 0; mi < 2; mi++)
#pragma unroll
                    for (int dg = 0; dg < 4; dg++) {
                        mma_bf16(o[mi][2 * dg],     al[mi], bh[dg]);
                        mma_bf16(o[mi][2 * dg + 1], al[mi], bh[dg] + 2);
                    }
            }
        }

        __syncthreads();
        if (kb + 2 <= qb) { fillKV(kb + 2, kb & 1); CP_COMMIT(); }
    }

    // ---- Reduce O partials across n-half warp pairs (overlay Q tiles+) ----
    __syncthreads();
    float* red = (float*)sm;              // 128 rows x 64 cols fp32 = 32KB
    if (nh == 1) {
#pragma unroll
        for (int mi = 0; mi < 2; mi++)
#pragma unroll
            for (int ni = 0; ni < 8; ni++) {
                const int col = ni * 8 + 2 * tq;
                const int row = m0 + mi * 16 + g;
                float2 v0 = {o[mi][ni][0], o[mi][ni][1]};
                float2 v1 = {o[mi][ni][2], o[mi][ni][3]};
                *(float2*)&red[row * 64 + col]       = v0;
                *(float2*)&red[(row + 8) * 64 + col] = v1;
            }
    }
    __syncthreads();

    if (nh == 0) {
#pragma unroll
        for (int mi = 0; mi < 2; mi++)
#pragma unroll
            for (int ni = 0; ni < 8; ni++) {
                const int col = ni * 8 + 2 * tq;
                const int row = m0 + mi * 16 + g;
                float2 v0 = *(const float2*)&red[row * 64 + col];
                float2 v1 = *(const float2*)&red[(row + 8) * 64 + col];
                const float c00 = o[mi][ni][0] + v0.x, c01 = o[mi][ni][1] + v0.y;
                const float c10 = o[mi][ni][2] + v1.x, c11 = o[mi][ni][3] + v1.y;
                const int gc = hoff + col;
                const size_t r0 = (size_t)(qrow0 + row) * DMODEL + gc;
                const size_t r1 = (size_t)(qrow0 + row + 8) * DMODEL + gc;
                *(uint32_t*)&Ohi[r0] = pack2_bf16(c00, c01);
                *(uint32_t*)&Olo[r0] = pack2_bf16(c00 - bf16_hi(c00), c01 - bf16_hi(c01));
                *(uint32_t*)&Ohi[r1] = pack2_bf16(c10, c11);
                *(uint32_t*)&Olo[r1] = pack2_bf16(c10 - bf16_hi(c10), c11 - bf16_hi(c11));
            }
    }
}

// ---------------------------------------------------------------------------
// Launch
// ---------------------------------------------------------------------------
extern "C" void kernel_launch(void* const* d_in, const int* in_sizes, int n_in,
                              void* d_out, int out_size)
{
    const float* x    = (const float*)d_in[0];
    const float* wq_w = (const float*)d_in[1];
    const float* wq_b = (const float*)d_in[2];
    const float* wk_w = (const float*)d_in[3];
    const float* wk_b = (const float*)d_in[4];
    const float* wv_w = (const float*)d_in[5];
    const float* wv_b = (const float*)d_in[6];
    const float* wo_w = (const float*)d_in[7];
    const float* wo_b = (const float*)d_in[8];
    float* out = (float*)d_out;

    __nv_bfloat16 *xhi, *xlo, *whi, *wlo;
    __nv_bfloat16 *Qhi, *Qlo, *Khi, *Klo, *Vhi, *Vlo, *AOhi, *AOlo;
    cudaGetSymbolAddress((void**)&xhi,  g_xhi);
    cudaGetSymbolAddress((void**)&xlo,  g_xlo);
    cudaGetSymbolAddress((void**)&whi,  g_whi);
    cudaGetSymbolAddress((void**)&wlo,  g_wlo);
    cudaGetSymbolAddress((void**)&Qhi,  g_Qhi);
    cudaGetSymbolAddress((void**)&Qlo,  g_Qlo);
    cudaGetSymbolAddress((void**)&Khi,  g_Khi);
    cudaGetSymbolAddress((void**)&Klo,  g_Klo);
    cudaGetSymbolAddress((void**)&Vhi,  g_Vhi);
    cudaGetSymbolAddress((void**)&Vlo,  g_Vlo);
    cudaGetSymbolAddress((void**)&AOhi, g_AOhi);
    cudaGetSymbolAddress((void**)&AOlo, g_AOlo);

    cudaFuncSetAttribute(mma_gemm_kernel,
                         cudaFuncAttributeMaxDynamicSharedMemorySize, GEMM_SMEM_B);
    cudaFuncSetAttribute(mma_attn_kernel,
                         cudaFuncAttributeMaxDynamicSharedMemorySize, ATTN_SMEM_B);

    const size_t WW = (size_t)DMODEL * DMODEL;

    // Split x + all 4 weights (weights fused into one launch)
    split_kernel<<<(MTOT * DMODEL / 4 + 255) / 256, 256>>>(x, xhi, xlo, MTOT * DMODEL / 4);
    {
        dim3 sgrid(((int)WW / 4 + 255) / 256, 4);
        split4_kernel<<<sgrid, 256>>>(wq_w, wk_w, wv_w, wo_w, whi, wlo, (int)WW / 4);
    }

    // Fused Q/K/V projections: CTA tile 256x128
    dim3 gqkv(DMODEL / 128, MTOT / 256, 3);     // (8, 16, 3)
    mma_gemm_kernel<<<gqkv, 256, GEMM_SMEM_B>>>(
        xhi, xlo, whi, wlo, wq_b, wk_b, wv_b,
        Qhi, Qlo, Khi, Klo, Vhi, Vlo, nullptr,
        MTOT, DMODEL, DMODEL, 1);

    dim3 agrid(SEQ / 128, NH, BATCH);           // (16, 16, 2)
    mma_attn_kernel<<<agrid, 256, ATTN_SMEM_B>>>(Qhi, Qlo, Khi, Klo, Vhi, Vlo, AOhi, AOlo);

    dim3 ggrid(DMODEL / 128, MTOT / 256, 1);    // (8, 16, 1)
    mma_gemm_kernel<<<ggrid, 256, GEMM_SMEM_B>>>(
        AOhi, AOlo, whi + 3 * WW, wlo + 3 * WW, wo_b, nullptr, nullptr,
        nullptr, nullptr, nullptr, nullptr, nullptr, nullptr, out,
        MTOT, DMODEL, DMODEL, 0);
}

// round 14
// speedup vs baseline: 1.0898x; 1.0078x over previous
#include <cuda_runtime.h>
#include <cuda_bf16.h>
#include <cstdint>
#include <cstddef>

// Problem constants
#define BATCH   2
#define SEQ     2048
#define DMODEL  1024
#define NH      16
#define DH      64
#define MTOT    (BATCH * SEQ)        // 4096 rows

// ---------------------------------------------------------------------------
// Scratch (device globals; no allocations allowed)
// ---------------------------------------------------------------------------
__device__ __nv_bfloat16 g_xhi [MTOT * DMODEL];
__device__ __nv_bfloat16 g_xlo [MTOT * DMODEL];
__device__ __nv_bfloat16 g_whi [4][DMODEL * DMODEL];
__device__ __nv_bfloat16 g_wlo [4][DMODEL * DMODEL];
__device__ __nv_bfloat16 g_Qhi [MTOT * DMODEL];
__device__ __nv_bfloat16 g_Qlo [MTOT * DMODEL];
__device__ __nv_bfloat16 g_Khi [MTOT * DMODEL];
__device__ __nv_bfloat16 g_Klo [MTOT * DMODEL];
__device__ __nv_bfloat16 g_Vhi [MTOT * DMODEL];
__device__ __nv_bfloat16 g_Vlo [MTOT * DMODEL];
__device__ __nv_bfloat16 g_AOhi[MTOT * DMODEL];
__device__ __nv_bfloat16 g_AOlo[MTOT * DMODEL];

// ---------------------------------------------------------------------------
// Helpers
// ---------------------------------------------------------------------------
__device__ __forceinline__ void mma_bf16(float* c, const uint32_t* a, const uint32_t* b) {
    asm volatile(
        "mma.sync.aligned.m16n8k16.row.col.f32.bf16.bf16.f32 "
        "{%0,%1,%2,%3}, {%4,%5,%6,%7}, {%8,%9}, {%0,%1,%2,%3};"
        : "+f"(c[0]), "+f"(c[1]), "+f"(c[2]), "+f"(c[3])
        : "r"(a[0]), "r"(a[1]), "r"(a[2]), "r"(a[3]),
          "r"(b[0]), "r"(b[1]));
}

__device__ __forceinline__ uint32_t pack2_bf16(float a, float b) {
    __nv_bfloat162 t = __floats2bfloat162_rn(a, b);
    return *(uint32_t*)&t;
}
__device__ __forceinline__ float bf16_hi(float x) {
    return __bfloat162float(__float2bfloat16(x));
}

__device__ __forceinline__ uint32_t smem_u32(const void* p) {
    uint32_t a;
    asm("{ .reg .u64 t; cvta.to.shared.u64 t, %1; cvt.u32.u64 %0, t; }"
        : "=r"(a) : "l"(p));
    return a;
}

__device__ __forceinline__ void cp16(uint32_t dst, const void* src) {
    asm volatile("cp.async.cg.shared.global [%0], [%1], 16;" :: "r"(dst), "l"(src));
}
#define CP_COMMIT() asm volatile("cp.async.commit_group;" ::: "memory")
#define CP_WAIT(n)  asm volatile("cp.async.wait_group %0;" :: "n"(n) : "memory")

__device__ __forceinline__ void ldsm_x4(uint32_t* r, uint32_t addr) {
    asm volatile("ldmatrix.sync.aligned.m8n8.x4.shared.b16 {%0,%1,%2,%3}, [%4];"
        : "=r"(r[0]), "=r"(r[1]), "=r"(r[2]), "=r"(r[3]) : "r"(addr));
}
__device__ __forceinline__ void ldsm_x4_t(uint32_t* r, uint32_t addr) {
    asm volatile("ldmatrix.sync.aligned.m8n8.x4.trans.shared.b16 {%0,%1,%2,%3}, [%4];"
        : "=r"(r[0]), "=r"(r[1]), "=r"(r[2]), "=r"(r[3]) : "r"(addr));
}

// ---------------------------------------------------------------------------
// Split kernels: fp32 -> bf16 hi + bf16 lo residual
// ---------------------------------------------------------------------------
__global__ void split_kernel(const float* __restrict__ src,
                             __nv_bfloat16* __restrict__ hi,
                             __nv_bfloat16* __restrict__ lo, int n4)
{
    int i = blockIdx.x * blockDim.x + threadIdx.x;
    if (i >= n4) return;
    float4 v = ((const float4*)src)[i];
    uint2 h, l;
    h.x = pack2_bf16(v.x, v.y);
    h.y = pack2_bf16(v.z, v.w);
    l.x = pack2_bf16(v.x - bf16_hi(v.x), v.y - bf16_hi(v.y));
    l.y = pack2_bf16(v.z - bf16_hi(v.z), v.w - bf16_hi(v.w));
    ((uint2*)hi)[i] = h;
    ((uint2*)lo)[i] = l;
}

__global__ void split4_kernel(const float* __restrict__ w0,
                              const float* __restrict__ w1,
                              const float* __restrict__ w2,
                              const float* __restrict__ w3,
                              __nv_bfloat16* __restrict__ hi,
                              __nv_bfloat16* __restrict__ lo,
                              int n4)
{
    const int z = blockIdx.y;
    const float* src = (z == 0) ? w0 : (z == 1) ? w1 : (z == 2) ? w2 : w3;
    int i = blockIdx.x * blockDim.x + threadIdx.x;
    if (i >= n4) return;
    float4 v = ((const float4*)src)[i];
    uint2 h, l;
    h.x = pack2_bf16(v.x, v.y);
    h.y = pack2_bf16(v.z, v.w);
    l.x = pack2_bf16(v.x - bf16_hi(v.x), v.y - bf16_hi(v.y));
    l.y = pack2_bf16(v.z - bf16_hi(v.z), v.w - bf16_hi(v.w));
    const size_t off = (size_t)z * ((size_t)DMODEL * DMODEL / 4);
    ((uint2*)hi)[off + i] = h;
    ((uint2*)lo)[off + i] = l;
}

// ===========================================================================
// Split-bf16 GEMM: CTA tile 256(M)x128(N), BK=64, 256 threads / 8 warps
// (4M x 2N, warp tile 64x64). 2-stage ring, ONE sync per chunk:
//   iter c: CP_WAIT(0); sync; prefetch c+1 into other stage; compute stage c.
// Safe: prefetch target was last read in iter c-1, ordered by this sync.
// ===========================================================================
#define GS 72
#define GT  (128 * GS)                 // 128-row tile (halves)
#define GTA (256 * GS)                 // 256-row tile (halves)
#define GSTG (2 * GTA + 2 * GT)        // one GEMM stage: Ahi Alo Bhi Blo
#define GEMM_SMEM_B (2 * GSTG * 2)     // 221184 B

__global__ __launch_bounds__(256, 1)
void mma_gemm_kernel(const __nv_bfloat16* __restrict__ Ah,
                     const __nv_bfloat16* __restrict__ Al,
                     const __nv_bfloat16* __restrict__ Wh,
                     const __nv_bfloat16* __restrict__ Wl,
                     const float* __restrict__ b0,
                     const float* __restrict__ b1,
                     const float* __restrict__ b2,
                     __nv_bfloat16* __restrict__ C0h, __nv_bfloat16* __restrict__ C0l,
                     __nv_bfloat16* __restrict__ C1h, __nv_bfloat16* __restrict__ C1l,
                     __nv_bfloat16* __restrict__ C2h, __nv_bfloat16* __restrict__ C2l,
                     float* __restrict__ Cf,
                     int M, int N, int K, int mode)
{
    extern __shared__ __nv_bfloat16 sm[];
    const uint32_t sb = smem_u32(sm);

    const int z = blockIdx.z;
    const __nv_bfloat16* Bh = Wh + (size_t)z * DMODEL * DMODEL;
    const __nv_bfloat16* Bl = Wl + (size_t)z * DMODEL * DMODEL;
    const float* bias = (z == 0) ? b0 : (z == 1) ? b1 : b2;
    __nv_bfloat16* Chi = (z == 0) ? C0h : (z == 1) ? C1h : C2h;
    __nv_bfloat16* Clo = (z == 0) ? C0l : (z == 1) ? C1l : C2l;

    const int t    = threadIdx.x;
    const int wid  = t >> 5;
    const int lane = t & 31;
    const int g    = lane >> 2;
    const int tq   = lane & 3;
    const int q    = lane >> 3;
    const int l8   = lane & 7;
    const int m0   = (wid >> 1) * 64;
    const int n0   = (wid & 1) * 64;

    const int bm = blockIdx.y * 256;
    const int bn = blockIdx.x * 128;

    float acc[4][8][4];
#pragma unroll
    for (int mi = 0; mi < 4; mi++)
#pragma unroll
        for (int ni = 0; ni < 8; ni++)
#pragma unroll
            for (int e = 0; e < 4; e++) acc[mi][ni][e] = 0.0f;

    const int NCHUNK = K / 64;    // 16

    auto fill = [&](int c, int s) {
        const int k0 = c * 64;
        const uint32_t SA = s * GSTG;
        const uint32_t SB_ = SA + 2 * GTA;
#pragma unroll
        for (int i = 0; i < 8; i++) {
            const int l   = i * 256 + t;
            const int row = l >> 3;
            const int seg = l & 7;
            const uint32_t d = sb + 2 * (SA + row * GS + seg * 8);
            const size_t   o = (size_t)(bm + row) * K + k0 + seg * 8;
            cp16(d,           Ah + o);
            cp16(d + 2 * GTA, Al + o);
        }
#pragma unroll
        for (int i = 0; i < 4; i++) {
            const int l   = i * 256 + t;
            const int row = l >> 3;
            const int seg = l & 7;
            const uint32_t d = sb + 2 * (SB_ + row * GS + seg * 8);
            const size_t   o = (size_t)(bn + row) * K + k0 + seg * 8;
            cp16(d,          Bh + o);
            cp16(d + 2 * GT, Bl + o);
        }
    };

    fill(0, 0); CP_COMMIT();

    for (int c = 0; c < NCHUNK; c++) {
        CP_WAIT(0);
        __syncthreads();
        if (c + 1 < NCHUNK) { fill(c + 1, (c + 1) & 1); CP_COMMIT(); }

        const uint32_t SA   = (c & 1) * GSTG;
        const uint32_t sAhi = sb + 2 * SA;
        const uint32_t sAlo = sAhi + 2 * GTA;
        const uint32_t sBhi = sAlo + 2 * GTA;
        const uint32_t sBlo = sBhi + 2 * GT;

#pragma unroll
        for (int ks = 0; ks < 4; ks++) {
            const int kk = ks * 16;

            uint32_t ah[4][4], al[4][4];
#pragma unroll
            for (int mi = 0; mi < 4; mi++) {
                const int arow = m0 + mi * 16 + (q & 1) * 8 + l8;
                const int acol = kk + (q >> 1) * 8;
                ldsm_x4(ah[mi], sAhi + 2 * (arow * GS + acol));
                ldsm_x4(al[mi], sAlo + 2 * (arow * GS + acol));
            }
#pragma unroll
            for (int p = 0; p < 2; p++) {
                uint32_t bh[2][4], bl[2][4];
#pragma unroll
                for (int j = 0; j < 2; j++) {
                    const int brow = n0 + (2 * p + j) * 16 + (q >> 1) * 8 + l8;
                    const int bcol = kk + (q & 1) * 8;
                    ldsm_x4(bh[j], sBhi + 2 * (brow * GS + bcol));
                    ldsm_x4(bl[j], sBlo + 2 * (brow * GS + bcol));
                }
                // pass hh (16 independent)
#pragma unroll
                for (int mi = 0; mi < 4; mi++)
#pragma unroll
                    for (int j = 0; j < 2; j++) {
                        const int ni = (2 * p + j) * 2;
                        mma_bf16(acc[mi][ni],     ah[mi], bh[j]);
                        mma_bf16(acc[mi][ni + 1], ah[mi], bh[j] + 2);
                    }
                // pass hl
#pragma unroll
                for (int mi = 0; mi < 4; mi++)
#pragma unroll
                    for (int j = 0; j < 2; j++) {
                        const int ni = (2 * p + j) * 2;
                        mma_bf16(acc[mi][ni],     ah[mi], bl[j]);
                        mma_bf16(acc[mi][ni + 1], ah[mi], bl[j] + 2);
                    }
                // pass lh
#pragma unroll
                for (int mi = 0; mi < 4; mi++)
#pragma unroll
                    for (int j = 0; j < 2; j++) {
                        const int ni = (2 * p + j) * 2;
                        mma_bf16(acc[mi][ni],     al[mi], bh[j]);
                        mma_bf16(acc[mi][ni + 1], al[mi], bh[j] + 2);
                    }
            }
        }
    }

    // Epilogue
#pragma unroll
    for (int mi = 0; mi < 4; mi++) {
        const int r0 = bm + m0 + mi * 16 + g;
#pragma unroll
        for (int ni = 0; ni < 8; ni++) {
            const int col = bn + n0 + ni * 8 + 2 * tq;
            const float bb0 = bias[col], bb1 = bias[col + 1];
            float c00 = acc[mi][ni][0] + bb0, c01 = acc[mi][ni][1] + bb1;
            float c10 = acc[mi][ni][2] + bb0, c11 = acc[mi][ni][3] + bb1;
            if (mode == 0) {
                float2 v0 = {c00, c01}, v1 = {c10, c11};
                *(float2*)&Cf[(size_t)r0 * N + col]       = v0;
                *(float2*)&Cf[(size_t)(r0 + 8) * N + col] = v1;
            } else {
                *(uint32_t*)&Chi[(size_t)r0 * N + col] = pack2_bf16(c00, c01);
                *(uint32_t*)&Clo[(size_t)r0 * N + col] =
                    pack2_bf16(c00 - bf16_hi(c00), c01 - bf16_hi(c01));
                *(uint32_t*)&Chi[(size_t)(r0 + 8) * N + col] = pack2_bf16(c10, c11);
                *(uint32_t*)&Clo[(size_t)(r0 + 8) * N + col] =
                    pack2_bf16(c10 - bf16_hi(c10), c11 - bf16_hi(c11));
            }
        }
    }
}

// ===========================================================================
// FA2-style split-bf16 causal attention: 256 threads / 8 warps as
// 4 q-groups (32 rows) x 2 n-halves (64 cols). Q fragments register-resident;
// fully-masked diagonal warp blocks skipped; 2-stage K/V ring with ONE sync
// per kb iteration (same pattern as GEMM).
// smem: Qhi@0 Qlo@GT; stage s: K@(2+4s) V@(4+4s).
// ===========================================================================
#define ATTN_SMEM_B (10 * GT * 2)     // 184320 B

__global__ __launch_bounds__(256, 1)
void mma_attn_kernel(const __nv_bfloat16* __restrict__ Qh,
                     const __nv_bfloat16* __restrict__ Ql,
                     const __nv_bfloat16* __restrict__ Kh,
                     const __nv_bfloat16* __restrict__ Kl,
                     const __nv_bfloat16* __restrict__ Vh,
                     const __nv_bfloat16* __restrict__ Vl,
                     __nv_bfloat16* __restrict__ Ohi,
                     __nv_bfloat16* __restrict__ Olo)
{
    extern __shared__ __nv_bfloat16 sm[];
    const uint32_t sb = smem_u32(sm);

    const int qb = (gridDim.x - 1) - blockIdx.x;   // heavy CTAs first
    const int h  = blockIdx.y;
    const int b  = blockIdx.z;

    const int t    = threadIdx.x;
    const int wid  = t >> 5;
    const int lane = t & 31;
    const int g    = lane >> 2;
    const int tq   = lane & 3;
    const int q    = lane >> 3;
    const int l8   = lane & 7;
    const int qw   = wid & 3;
    const int nh   = wid >> 2;
    const int m0   = qw * 32;
    const int nc0  = nh * 64;
    const bool diag_skip = (nc0 >= m0 + 32);

    const int hoff  = h * DH;
    const int brow0 = b * SEQ;
    const int qrow0 = brow0 + qb * 128;

    auto fillKV = [&](int kb, int s) {
        const int krow0 = brow0 + kb * 128;
        const uint32_t SK = (2 + 4 * s) * GT;
        const uint32_t SV = (4 + 4 * s) * GT;
#pragma unroll
        for (int i = 0; i < 4; i++) {
            const int l   = i * 256 + t;
            const int row = l >> 3;
            const int seg = l & 7;
            const uint32_t off = row * GS + seg * 8;
            const size_t   sidx = (size_t)(krow0 + row) * DMODEL + hoff + seg * 8;
            cp16(sb + 2 * (SK + off),      Kh + sidx);
            cp16(sb + 2 * (SK + GT + off), Kl + sidx);
            cp16(sb + 2 * (SV + off),      Vh + sidx);
            cp16(sb + 2 * (SV + GT + off), Vl + sidx);
        }
    };

    // ---- prologue: Q + KV stage 0 in one group ----
#pragma unroll
    for (int i = 0; i < 4; i++) {
        const int l   = i * 256 + t;
        const int row = l >> 3;
        const int seg = l & 7;
        const uint32_t d = sb + 2 * (row * GS + seg * 8);
        const size_t   o = (size_t)(qrow0 + row) * DMODEL + hoff + seg * 8;
        cp16(d,          Qh + o);
        cp16(d + 2 * GT, Ql + o);
    }
    fillKV(0, 0);
    CP_COMMIT();

    uint32_t qfh[4][2][4], qfl[4][2][4];   // [ks][mi]

    float o[2][8][4];
#pragma unroll
    for (int mi = 0; mi < 2; mi++)
#pragma unroll
        for (int ni = 0; ni < 8; ni++)
#pragma unroll
            for (int e = 0; e < 4; e++) o[mi][ni][e] = 0.0f;

    for (int kb = 0; kb <= qb; kb++) {
        CP_WAIT(0);
        __syncthreads();
        if (kb + 1 <= qb) { fillKV(kb + 1, (kb + 1) & 1); CP_COMMIT(); }

        if (kb == 0) {
            // Q fragments register-resident for the whole loop
#pragma unroll
            for (int ks = 0; ks < 4; ks++)
#pragma unroll
                for (int mi = 0; mi < 2; mi++) {
                    const int arow = m0 + mi * 16 + (q & 1) * 8 + l8;
                    const int acol = ks * 16 + (q >> 1) * 8;
                    ldsm_x4(qfh[ks][mi], sb + 2 * (arow * GS + acol));
                    ldsm_x4(qfl[ks][mi], sb + 2 * (GT + arow * GS + acol));
                }
        }

        const bool active = !(kb == qb && diag_skip);

        if (active) {
            const uint32_t SK   = (2 + 4 * (kb & 1)) * GT;
            const uint32_t SV   = (4 + 4 * (kb & 1)) * GT;
            const uint32_t sKhi = sb + 2 * SK;
            const uint32_t sKlo = sKhi + 2 * GT;
            const uint32_t sVhi = sb + 2 * SV;
            const uint32_t sVlo = sVhi + 2 * GT;

            // ---- Phase 1: S[32 x 64] (this warp's n-half) ----
            float s[2][8][4];
#pragma unroll
            for (int mi = 0; mi < 2; mi++)
#pragma unroll
                for (int nt = 0; nt < 8; nt++)
#pragma unroll
                    for (int e = 0; e < 4; e++) s[mi][nt][e] = 0.0f;

#pragma unroll
            for (int ks = 0; ks < 4; ks++) {
                const int kk = ks * 16;
                uint32_t bh[4][4], bl[4][4];
#pragma unroll
                for (int j = 0; j < 4; j++) {
                    const int brow = nc0 + j * 16 + (q >> 1) * 8 + l8;
                    const int bcol = kk + (q & 1) * 8;
                    ldsm_x4(bh[j], sKhi + 2 * (brow * GS + bcol));
                    ldsm_x4(bl[j], sKlo + 2 * (brow * GS + bcol));
                }
                // pass hh (16 independent)
#pragma unroll
                for (int mi = 0; mi < 2; mi++)
#pragma unroll
                    for (int j = 0; j < 4; j++) {
                        mma_bf16(s[mi][2 * j],     qfh[ks][mi], bh[j]);
                        mma_bf16(s[mi][2 * j + 1], qfh[ks][mi], bh[j] + 2);
                    }
                // pass hl
#pragma unroll
                for (int mi = 0; mi < 2; mi++)
#pragma unroll
                    for (int j = 0; j < 4; j++) {
                        mma_bf16(s[mi][2 * j],     qfh[ks][mi], bl[j]);
                        mma_bf16(s[mi][2 * j + 1], qfh[ks][mi], bl[j] + 2);
                    }
                // pass lh
#pragma unroll
                for (int mi = 0; mi < 2; mi++)
#pragma unroll
                    for (int j = 0; j < 4; j++) {
                        mma_bf16(s[mi][2 * j],     qfl[ks][mi], bh[j]);
                        mma_bf16(s[mi][2 * j + 1], qfl[ks][mi], bh[j] + 2);
                    }
            }

            // Diagonal-block causal mask: keep col <= row
            if (kb == qb) {
#pragma unroll
                for (int mi = 0; mi < 2; mi++) {
                    const int r0 = m0 + mi * 16 + g, r1 = r0 + 8;
#pragma unroll
                    for (int nt = 0; nt < 8; nt++) {
                        const int c0 = nc0 + nt * 8 + 2 * tq;
                        if (c0     > r0) s[mi][nt][0] = 0.0f;
                        if (c0 + 1 > r0) s[mi][nt][1] = 0.0f;
                        if (c0     > r1) s[mi][nt][2] = 0.0f;
                        if (c0 + 1 > r1) s[mi][nt][3] = 0.0f;
                    }
                }
            }

            // ---- Phase 2: O[32 x 64] += S(n-half) @ V(n-half rows) ----
#pragma unroll
            for (int kc = 0; kc < 4; kc++) {
                uint32_t ah[2][4], al[2][4];
#pragma unroll
                for (int mi = 0; mi < 2; mi++) {
                    const float v0 = s[mi][2 * kc][0],     v1 = s[mi][2 * kc][1];
                    const float v2 = s[mi][2 * kc][2],     v3 = s[mi][2 * kc][3];
                    const float w0 = s[mi][2 * kc + 1][0], w1 = s[mi][2 * kc + 1][1];
                    const float w2 = s[mi][2 * kc + 1][2], w3 = s[mi][2 * kc + 1][3];
                    ah[mi][0] = pack2_bf16(v0, v1);
                    ah[mi][1] = pack2_bf16(v2, v3);
                    ah[mi][2] = pack2_bf16(w0, w1);
                    ah[mi][3] = pack2_bf16(w2, w3);
                    al[mi][0] = pack2_bf16(v0 - bf16_hi(v0), v1 - bf16_hi(v1));
                    al[mi][1] = pack2_bf16(v2 - bf16_hi(v2), v3 - bf16_hi(v3));
                    al[mi][2] = pack2_bf16(w0 - bf16_hi(w0), w1 - bf16_hi(w1));
                    al[mi][3] = pack2_bf16(w2 - bf16_hi(w2), w3 - bf16_hi(w3));
                }
                const int vr = nc0 + kc * 16 + (q & 1) * 8 + l8;
                uint32_t bh[4][4], bl[4][4];
#pragma unroll
                for (int dg = 0; dg < 4; dg++) {
                    const int vcol = dg * 16 + (q >> 1) * 8;
                    ldsm_x4_t(bh[dg], sVhi + 2 * (vr * GS + vcol));
                    ldsm_x4_t(bl[dg], sVlo + 2 * (vr * GS + vcol));
                }
                // pass hh (16 independent)
#pragma unroll
                for (int mi = 0; mi < 2; mi++)
#pragma unroll
                    for (int dg = 0; dg < 4; dg++) {
                        mma_bf16(o[mi][2 * dg],     ah[mi], bh[dg]);
                        mma_bf16(o[mi][2 * dg + 1], ah[mi], bh[dg] + 2);
                    }
                // pass hl
#pragma unroll
                for (int mi = 0; mi < 2; mi++)
#pragma unroll
                    for (int dg = 0; dg < 4; dg++) {
                        mma_bf16(o[mi][2 * dg],     ah[mi], bl[dg]);
                        mma_bf16(o[mi][2 * dg + 1], ah[mi], bl[dg] + 2);
                    }
                // pass lh
#pragma unroll
                for (int mi = 0; mi < 2; mi++)
#pragma unroll
                    for (int dg = 0; dg < 4; dg++) {
                        mma_bf16(o[mi][2 * dg],     al[mi], bh[dg]);
                        mma_bf16(o[mi][2 * dg + 1], al[mi], bh[dg] + 2);
                    }
            }
        }
    }

    // ---- Reduce O partials across n-half warp pairs (overlay Q tiles+) ----
    __syncthreads();
    float* red = (float*)sm;              // 128 rows x 64 cols fp32 = 32KB
    if (nh == 1) {
#pragma unroll
        for (int mi = 0; mi < 2; mi++)
#pragma unroll
            for (int ni = 0; ni < 8; ni++) {
                const int col = ni * 8 + 2 * tq;
                const int row = m0 + mi * 16 + g;
                float2 v0 = {o[mi][ni][0], o[mi][ni][1]};
                float2 v1 = {o[mi][ni][2], o[mi][ni][3]};
                *(float2*)&red[row * 64 + col]       = v0;
                *(float2*)&red[(row + 8) * 64 + col] = v1;
            }
    }
    __syncthreads();

    if (nh == 0) {
#pragma unroll
        for (int mi = 0; mi < 2; mi++)
#pragma unroll
            for (int ni = 0; ni < 8; ni++) {
                const int col = ni * 8 + 2 * tq;
                const int row = m0 + mi * 16 + g;
                float2 v0 = *(const float2*)&red[row * 64 + col];
                float2 v1 = *(const float2*)&red[(row + 8) * 64 + col];
                const float c00 = o[mi][ni][0] + v0.x, c01 = o[mi][ni][1] + v0.y;
                const float c10 = o[mi][ni][2] + v1.x, c11 = o[mi][ni][3] + v1.y;
                const int gc = hoff + col;
                const size_t r0 = (size_t)(qrow0 + row) * DMODEL + gc;
                const size_t r1 = (size_t)(qrow0 + row + 8) * DMODEL + gc;
                *(uint32_t*)&Ohi[r0] = pack2_bf16(c00, c01);
                *(uint32_t*)&Olo[r0] = pack2_bf16(c00 - bf16_hi(c00), c01 - bf16_hi(c01));
                *(uint32_t*)&Ohi[r1] = pack2_bf16(c10, c11);
                *(uint32_t*)&Olo[r1] = pack2_bf16(c10 - bf16_hi(c10), c11 - bf16_hi(c11));
            }
    }
}

// ---------------------------------------------------------------------------
// Launch
// ---------------------------------------------------------------------------
extern "C" void kernel_launch(void* const* d_in, const int* in_sizes, int n_in,
                              void* d_out, int out_size)
{
    const float* x    = (const float*)d_in[0];
    const float* wq_w = (const float*)d_in[1];
    const float* wq_b = (const float*)d_in[2];
    const float* wk_w = (const float*)d_in[3];
    const float* wk_b = (const float*)d_in[4];
    const float* wv_w = (const float*)d_in[5];
    const float* wv_b = (const float*)d_in[6];
    const float* wo_w = (const float*)d_in[7];
    const float* wo_b = (const float*)d_in[8];
    float* out = (float*)d_out;

    __nv_bfloat16 *xhi, *xlo, *whi, *wlo;
    __nv_bfloat16 *Qhi, *Qlo, *Khi, *Klo, *Vhi, *Vlo, *AOhi, *AOlo;
    cudaGetSymbolAddress((void**)&xhi,  g_xhi);
    cudaGetSymbolAddress((void**)&xlo,  g_xlo);
    cudaGetSymbolAddress((void**)&whi,  g_whi);
    cudaGetSymbolAddress((void**)&wlo,  g_wlo);
    cudaGetSymbolAddress((void**)&Qhi,  g_Qhi);
    cudaGetSymbolAddress((void**)&Qlo,  g_Qlo);
    cudaGetSymbolAddress((void**)&Khi,  g_Khi);
    cudaGetSymbolAddress((void**)&Klo,  g_Klo);
    cudaGetSymbolAddress((void**)&Vhi,  g_Vhi);
    cudaGetSymbolAddress((void**)&Vlo,  g_Vlo);
    cudaGetSymbolAddress((void**)&AOhi, g_AOhi);
    cudaGetSymbolAddress((void**)&AOlo, g_AOlo);

    cudaFuncSetAttribute(mma_gemm_kernel,
                         cudaFuncAttributeMaxDynamicSharedMemorySize, GEMM_SMEM_B);
    cudaFuncSetAttribute(mma_attn_kernel,
                         cudaFuncAttributeMaxDynamicSharedMemorySize, ATTN_SMEM_B);

    const size_t WW = (size_t)DMODEL * DMODEL;

    split_kernel<<<(MTOT * DMODEL / 4 + 255) / 256, 256>>>(x, xhi, xlo, MTOT * DMODEL / 4);
    {
        dim3 sgrid(((int)WW / 4 + 255) / 256, 4);
        split4_kernel<<<sgrid, 256>>>(wq_w, wk_w, wv_w, wo_w, whi, wlo, (int)WW / 4);
    }

    // Fused Q/K/V projections: CTA tile 256x128
    dim3 gqkv(DMODEL / 128, MTOT / 256, 3);     // (8, 16, 3)
    mma_gemm_kernel<<<gqkv, 256, GEMM_SMEM_B>>>(
        xhi, xlo, whi, wlo, wq_b, wk_b, wv_b,
        Qhi, Qlo, Khi, Klo, Vhi, Vlo, nullptr,
        MTOT, DMODEL, DMODEL, 1);

    dim3 agrid(SEQ / 128, NH, BATCH);           // (16, 16, 2)
    mma_attn_kernel<<<agrid, 256, ATTN_SMEM_B>>>(Qhi, Qlo, Khi, Klo, Vhi, Vlo, AOhi, AOlo);

    dim3 ggrid(DMODEL / 128, MTOT / 256, 1);    // (8, 16, 1)
    mma_gemm_kernel<<<ggrid, 256, GEMM_SMEM_B>>>(
        AOhi, AOlo, whi + 3 * WW, wlo + 3 * WW, wo_b, nullptr, nullptr,
        nullptr, nullptr, nullptr, nullptr, nullptr, nullptr, out,
        MTOT, DMODEL, DMODEL, 0);
}

// round 16
// speedup vs baseline: 1.2024x; 1.1033x over previous
#include <cuda_runtime.h>
#include <cuda_bf16.h>
#include <cuda_fp16.h>
#include <cstdint>
#include <cstddef>

// Problem constants
#define BATCH   2
#define SEQ     2048
#define DMODEL  1024
#define NH      16
#define DH      64
#define MTOT    (BATCH * SEQ)        // 4096 rows

// ---------------------------------------------------------------------------
// Scratch (device globals; 16-bit payloads, type tag is nominal)
// ---------------------------------------------------------------------------
__device__ __nv_bfloat16 g_xhi [MTOT * DMODEL];
__device__ __nv_bfloat16 g_xlo [MTOT * DMODEL];
__device__ __nv_bfloat16 g_whi [4][DMODEL * DMODEL];
__device__ __nv_bfloat16 g_wlo [4][DMODEL * DMODEL];
__device__ __nv_bfloat16 g_Qhi [MTOT * DMODEL];   // fp16 payload
__device__ __nv_bfloat16 g_Qlo [MTOT * DMODEL];   // fp16 payload (unused by attn)
__device__ __nv_bfloat16 g_Khi [MTOT * DMODEL];   // fp16 payload
__device__ __nv_bfloat16 g_Klo [MTOT * DMODEL];   // fp16 payload
__device__ __nv_bfloat16 g_Vhi [MTOT * DMODEL];   // fp16 payload
__device__ __nv_bfloat16 g_Vlo [MTOT * DMODEL];   // fp16 payload
__device__ __nv_bfloat16 g_AOhi[MTOT * DMODEL];   // bf16 (feeds WO gemm)
__device__ __nv_bfloat16 g_AOlo[MTOT * DMODEL];   // bf16

// ---------------------------------------------------------------------------
// Helpers
// ---------------------------------------------------------------------------
__device__ __forceinline__ void mma_bf16(float* c, const uint32_t* a, const uint32_t* b) {
    asm volatile(
        "mma.sync.aligned.m16n8k16.row.col.f32.bf16.bf16.f32 "
        "{%0,%1,%2,%3}, {%4,%5,%6,%7}, {%8,%9}, {%0,%1,%2,%3};"
        : "+f"(c[0]), "+f"(c[1]), "+f"(c[2]), "+f"(c[3])
        : "r"(a[0]), "r"(a[1]), "r"(a[2]), "r"(a[3]),
          "r"(b[0]), "r"(b[1]));
}
__device__ __forceinline__ void mma_f16(float* c, const uint32_t* a, const uint32_t* b) {
    asm volatile(
        "mma.sync.aligned.m16n8k16.row.col.f32.f16.f16.f32 "
        "{%0,%1,%2,%3}, {%4,%5,%6,%7}, {%8,%9}, {%0,%1,%2,%3};"
        : "+f"(c[0]), "+f"(c[1]), "+f"(c[2]), "+f"(c[3])
        : "r"(a[0]), "r"(a[1]), "r"(a[2]), "r"(a[3]),
          "r"(b[0]), "r"(b[1]));
}

__device__ __forceinline__ uint32_t pack2_bf16(float a, float b) {
    __nv_bfloat162 t = __floats2bfloat162_rn(a, b);
    return *(uint32_t*)&t;
}
__device__ __forceinline__ float bf16_hi(float x) {
    return __bfloat162float(__float2bfloat16(x));
}
__device__ __forceinline__ uint32_t pack2_f16(float a, float b) {
    __half2 t = __floats2half2_rn(a, b);
    return *(uint32_t*)&t;
}
__device__ __forceinline__ float f16_hi(float x) {
    return __half2float(__float2half_rn(x));
}

__device__ __forceinline__ uint32_t smem_u32(const void* p) {
    uint32_t a;
    asm("{ .reg .u64 t; cvta.to.shared.u64 t, %1; cvt.u32.u64 %0, t; }"
        : "=r"(a) : "l"(p));
    return a;
}

__device__ __forceinline__ void cp16(uint32_t dst, const void* src) {
    asm volatile("cp.async.cg.shared.global [%0], [%1], 16;" :: "r"(dst), "l"(src));
}
#define CP_COMMIT() asm volatile("cp.async.commit_group;" ::: "memory")
#define CP_WAIT(n)  asm volatile("cp.async.wait_group %0;" :: "n"(n) : "memory")

__device__ __forceinline__ void ldsm_x4(uint32_t* r, uint32_t addr) {
    asm volatile("ldmatrix.sync.aligned.m8n8.x4.shared.b16 {%0,%1,%2,%3}, [%4];"
        : "=r"(r[0]), "=r"(r[1]), "=r"(r[2]), "=r"(r[3]) : "r"(addr));
}
__device__ __forceinline__ void ldsm_x4_t(uint32_t* r, uint32_t addr) {
    asm volatile("ldmatrix.sync.aligned.m8n8.x4.trans.shared.b16 {%0,%1,%2,%3}, [%4];"
        : "=r"(r[0]), "=r"(r[1]), "=r"(r[2]), "=r"(r[3]) : "r"(addr));
}

// ---------------------------------------------------------------------------
// Split kernels: fp32 -> bf16 hi + bf16 lo residual (for GEMM inputs)
// ---------------------------------------------------------------------------
__global__ void split_kernel(const float* __restrict__ src,
                             __nv_bfloat16* __restrict__ hi,
                             __nv_bfloat16* __restrict__ lo, int n4)
{
    int i = blockIdx.x * blockDim.x + threadIdx.x;
    if (i >= n4) return;
    float4 v = ((const float4*)src)[i];
    uint2 h, l;
    h.x = pack2_bf16(v.x, v.y);
    h.y = pack2_bf16(v.z, v.w);
    l.x = pack2_bf16(v.x - bf16_hi(v.x), v.y - bf16_hi(v.y));
    l.y = pack2_bf16(v.z - bf16_hi(v.z), v.w - bf16_hi(v.w));
    ((uint2*)hi)[i] = h;
    ((uint2*)lo)[i] = l;
}

__global__ void split4_kernel(const float* __restrict__ w0,
                              const float* __restrict__ w1,
                              const float* __restrict__ w2,
                              const float* __restrict__ w3,
                              __nv_bfloat16* __restrict__ hi,
                              __nv_bfloat16* __restrict__ lo,
                              int n4)
{
    const int z = blockIdx.y;
    const float* src = (z == 0) ? w0 : (z == 1) ? w1 : (z == 2) ? w2 : w3;
    int i = blockIdx.x * blockDim.x + threadIdx.x;
    if (i >= n4) return;
    float4 v = ((const float4*)src)[i];
    uint2 h, l;
    h.x = pack2_bf16(v.x, v.y);
    h.y = pack2_bf16(v.z, v.w);
    l.x = pack2_bf16(v.x - bf16_hi(v.x), v.y - bf16_hi(v.y));
    l.y = pack2_bf16(v.z - bf16_hi(v.z), v.w - bf16_hi(v.w));
    const size_t off = (size_t)z * ((size_t)DMODEL * DMODEL / 4);
    ((uint2*)hi)[off + i] = h;
    ((uint2*)lo)[off + i] = l;
}

// ===========================================================================
// Split-bf16 GEMM (inputs bf16 hi/lo, 3 passes, fp32 accum).
// CTA 256x128, BK=64, 8 warps (4M x 2N, warp tile 64x64), 2-stage ring,
// one sync per chunk.
// mode 0: fp32 C.  mode 1: fp16 hi/lo split C (consumed by fp16 attention).
// ===========================================================================
#define GS 72
#define GT  (128 * GS)
#define GTA (256 * GS)
#define GSTG (2 * GTA + 2 * GT)
#define GEMM_SMEM_B (2 * GSTG * 2)     // 221184 B

__global__ __launch_bounds__(256, 1)
void mma_gemm_kernel(const __nv_bfloat16* __restrict__ Ah,
                     const __nv_bfloat16* __restrict__ Al,
                     const __nv_bfloat16* __restrict__ Wh,
                     const __nv_bfloat16* __restrict__ Wl,
                     const float* __restrict__ b0,
                     const float* __restrict__ b1,
                     const float* __restrict__ b2,
                     __nv_bfloat16* __restrict__ C0h, __nv_bfloat16* __restrict__ C0l,
                     __nv_bfloat16* __restrict__ C1h, __nv_bfloat16* __restrict__ C1l,
                     __nv_bfloat16* __restrict__ C2h, __nv_bfloat16* __restrict__ C2l,
                     float* __restrict__ Cf,
                     int M, int N, int K, int mode)
{
    extern __shared__ __nv_bfloat16 sm[];
    const uint32_t sb = smem_u32(sm);

    const int z = blockIdx.z;
    const __nv_bfloat16* Bh = Wh + (size_t)z * DMODEL * DMODEL;
    const __nv_bfloat16* Bl = Wl + (size_t)z * DMODEL * DMODEL;
    const float* bias = (z == 0) ? b0 : (z == 1) ? b1 : b2;
    __nv_bfloat16* Chi = (z == 0) ? C0h : (z == 1) ? C1h : C2h;
    __nv_bfloat16* Clo = (z == 0) ? C0l : (z == 1) ? C1l : C2l;

    const int t    = threadIdx.x;
    const int wid  = t >> 5;
    const int lane = t & 31;
    const int g    = lane >> 2;
    const int tq   = lane & 3;
    const int q    = lane >> 3;
    const int l8   = lane & 7;
    const int m0   = (wid >> 1) * 64;
    const int n0   = (wid & 1) * 64;

    const int bm = blockIdx.y * 256;
    const int bn = blockIdx.x * 128;

    float acc[4][8][4];
#pragma unroll
    for (int mi = 0; mi < 4; mi++)
#pragma unroll
        for (int ni = 0; ni < 8; ni++)
#pragma unroll
            for (int e = 0; e < 4; e++) acc[mi][ni][e] = 0.0f;

    const int NCHUNK = K / 64;    // 16

    auto fill = [&](int c, int s) {
        const int k0 = c * 64;
        const uint32_t SA = s * GSTG;
        const uint32_t SB_ = SA + 2 * GTA;
#pragma unroll
        for (int i = 0; i < 8; i++) {
            const int l   = i * 256 + t;
            const int row = l >> 3;
            const int seg = l & 7;
            const uint32_t d = sb + 2 * (SA + row * GS + seg * 8);
            const size_t   o = (size_t)(bm + row) * K + k0 + seg * 8;
            cp16(d,           Ah + o);
            cp16(d + 2 * GTA, Al + o);
        }
#pragma unroll
        for (int i = 0; i < 4; i++) {
            const int l   = i * 256 + t;
            const int row = l >> 3;
            const int seg = l & 7;
            const uint32_t d = sb + 2 * (SB_ + row * GS + seg * 8);
            const size_t   o = (size_t)(bn + row) * K + k0 + seg * 8;
            cp16(d,          Bh + o);
            cp16(d + 2 * GT, Bl + o);
        }
    };

    fill(0, 0); CP_COMMIT();

    for (int c = 0; c < NCHUNK; c++) {
        CP_WAIT(0);
        __syncthreads();
        if (c + 1 < NCHUNK) { fill(c + 1, (c + 1) & 1); CP_COMMIT(); }

        const uint32_t SA   = (c & 1) * GSTG;
        const uint32_t sAhi = sb + 2 * SA;
        const uint32_t sAlo = sAhi + 2 * GTA;
        const uint32_t sBhi = sAlo + 2 * GTA;
        const uint32_t sBlo = sBhi + 2 * GT;

#pragma unroll
        for (int ks = 0; ks < 4; ks++) {
            const int kk = ks * 16;

            uint32_t ah[4][4], al[4][4];
#pragma unroll
            for (int mi = 0; mi < 4; mi++) {
                const int arow = m0 + mi * 16 + (q & 1) * 8 + l8;
                const int acol = kk + (q >> 1) * 8;
                ldsm_x4(ah[mi], sAhi + 2 * (arow * GS + acol));
                ldsm_x4(al[mi], sAlo + 2 * (arow * GS + acol));
            }
#pragma unroll
            for (int p = 0; p < 2; p++) {
                uint32_t bh[2][4], bl[2][4];
#pragma unroll
                for (int j = 0; j < 2; j++) {
                    const int brow = n0 + (2 * p + j) * 16 + (q >> 1) * 8 + l8;
                    const int bcol = kk + (q & 1) * 8;
                    ldsm_x4(bh[j], sBhi + 2 * (brow * GS + bcol));
                    ldsm_x4(bl[j], sBlo + 2 * (brow * GS + bcol));
                }
                // pass hh
#pragma unroll
                for (int mi = 0; mi < 4; mi++)
#pragma unroll
                    for (int j = 0; j < 2; j++) {
                        const int ni = (2 * p + j) * 2;
                        mma_bf16(acc[mi][ni],     ah[mi], bh[j]);
                        mma_bf16(acc[mi][ni + 1], ah[mi], bh[j] + 2);
                    }
                // pass hl
#pragma unroll
                for (int mi = 0; mi < 4; mi++)
#pragma unroll
                    for (int j = 0; j < 2; j++) {
                        const int ni = (2 * p + j) * 2;
                        mma_bf16(acc[mi][ni],     ah[mi], bl[j]);
                        mma_bf16(acc[mi][ni + 1], ah[mi], bl[j] + 2);
                    }
                // pass lh
#pragma unroll
                for (int mi = 0; mi < 4; mi++)
#pragma unroll
                    for (int j = 0; j < 2; j++) {
                        const int ni = (2 * p + j) * 2;
                        mma_bf16(acc[mi][ni],     al[mi], bh[j]);
                        mma_bf16(acc[mi][ni + 1], al[mi], bh[j] + 2);
                    }
            }
        }
    }

    // Epilogue
#pragma unroll
    for (int mi = 0; mi < 4; mi++) {
        const int r0 = bm + m0 + mi * 16 + g;
#pragma unroll
        for (int ni = 0; ni < 8; ni++) {
            const int col = bn + n0 + ni * 8 + 2 * tq;
            const float bb0 = bias[col], bb1 = bias[col + 1];
            float c00 = acc[mi][ni][0] + bb0, c01 = acc[mi][ni][1] + bb1;
            float c10 = acc[mi][ni][2] + bb0, c11 = acc[mi][ni][3] + bb1;
            if (mode == 0) {
                float2 v0 = {c00, c01}, v1 = {c10, c11};
                *(float2*)&Cf[(size_t)r0 * N + col]       = v0;
                *(float2*)&Cf[(size_t)(r0 + 8) * N + col] = v1;
            } else {
                // fp16 split (consumed by fp16 attention)
                *(uint32_t*)&Chi[(size_t)r0 * N + col] = pack2_f16(c00, c01);
                *(uint32_t*)&Clo[(size_t)r0 * N + col] =
                    pack2_f16(c00 - f16_hi(c00), c01 - f16_hi(c01));
                *(uint32_t*)&Chi[(size_t)(r0 + 8) * N + col] = pack2_f16(c10, c11);
                *(uint32_t*)&Clo[(size_t)(r0 + 8) * N + col] =
                    pack2_f16(c10 - f16_hi(c10), c11 - f16_hi(c11));
            }
        }
    }
}

// ===========================================================================
// fp16 2-pass causal attention (no softmax). 256 threads / 8 warps as
// 4 q-groups (32 rows) x 2 n-halves (64 cols).
// S = Qh*Kh + Qh*Kl  (Q truncated to fp16-hi; err ~2^-12)
// O = Sh*Vh + Sh*Vl  (S truncated to fp16-hi; err ~2^-12)
// Q fragments (hi only) register-resident; diag-skip; 2-stage KV ring,
// one sync per kb. smem: Qh@0; stage s: K@(1+4s) (hi,lo), V@(3+4s) (hi,lo).
// Epilogue writes AO as bf16 hi/lo for the bf16 WO GEMM.
// ===========================================================================
#define ATTN_SMEM_B (9 * GT * 2)      // 165888 B

__global__ __launch_bounds__(256, 1)
void mma_attn_kernel(const __nv_bfloat16* __restrict__ Qh,
                     const __nv_bfloat16* __restrict__ Kh,
                     const __nv_bfloat16* __restrict__ Kl,
                     const __nv_bfloat16* __restrict__ Vh,
                     const __nv_bfloat16* __restrict__ Vl,
                     __nv_bfloat16* __restrict__ Ohi,
                     __nv_bfloat16* __restrict__ Olo)
{
    extern __shared__ __nv_bfloat16 sm[];
    const uint32_t sb = smem_u32(sm);

    const int qb = (gridDim.x - 1) - blockIdx.x;   // heavy CTAs first
    const int h  = blockIdx.y;
    const int b  = blockIdx.z;

    const int t    = threadIdx.x;
    const int wid  = t >> 5;
    const int lane = t & 31;
    const int g    = lane >> 2;
    const int tq   = lane & 3;
    const int q    = lane >> 3;
    const int l8   = lane & 7;
    const int qw   = wid & 3;
    const int nh   = wid >> 2;
    const int m0   = qw * 32;
    const int nc0  = nh * 64;
    const bool diag_skip = (nc0 >= m0 + 32);

    const int hoff  = h * DH;
    const int brow0 = b * SEQ;
    const int qrow0 = brow0 + qb * 128;

    auto fillKV = [&](int kb, int s) {
        const int krow0 = brow0 + kb * 128;
        const uint32_t SK = (1 + 4 * s) * GT;
        const uint32_t SV = (3 + 4 * s) * GT;
#pragma unroll
        for (int i = 0; i < 4; i++) {
            const int l   = i * 256 + t;
            const int row = l >> 3;
            const int seg = l & 7;
            const uint32_t off = row * GS + seg * 8;
            const size_t   sidx = (size_t)(krow0 + row) * DMODEL + hoff + seg * 8;
            cp16(sb + 2 * (SK + off),      Kh + sidx);
            cp16(sb + 2 * (SK + GT + off), Kl + sidx);
            cp16(sb + 2 * (SV + off),      Vh + sidx);
            cp16(sb + 2 * (SV + GT + off), Vl + sidx);
        }
    };

    // ---- prologue: Qh (128 rows x 8 segs = 1024 slots) + KV stage 0 ----
#pragma unroll
    for (int i = 0; i < 4; i++) {
        const int l   = i * 256 + t;
        const int row = l >> 3;
        const int seg = l & 7;
        const uint32_t d = sb + 2 * (row * GS + seg * 8);
        const size_t   o = (size_t)(qrow0 + row) * DMODEL + hoff + seg * 8;
        cp16(d, Qh + o);
    }
    fillKV(0, 0);
    CP_COMMIT();

    uint32_t qfh[4][2][4];   // [ks][mi], fp16 hi fragments only

    float o[2][8][4];
#pragma unroll
    for (int mi = 0; mi < 2; mi++)
#pragma unroll
        for (int ni = 0; ni < 8; ni++)
#pragma unroll
            for (int e = 0; e < 4; e++) o[mi][ni][e] = 0.0f;

    for (int kb = 0; kb <= qb; kb++) {
        CP_WAIT(0);
        __syncthreads();
        if (kb + 1 <= qb) { fillKV(kb + 1, (kb + 1) & 1); CP_COMMIT(); }

        if (kb == 0) {
#pragma unroll
            for (int ks = 0; ks < 4; ks++)
#pragma unroll
                for (int mi = 0; mi < 2; mi++) {
                    const int arow = m0 + mi * 16 + (q & 1) * 8 + l8;
                    const int acol = ks * 16 + (q >> 1) * 8;
                    ldsm_x4(qfh[ks][mi], sb + 2 * (arow * GS + acol));
                }
        }

        const bool active = !(kb == qb && diag_skip);

        if (active) {
            const uint32_t SK   = (1 + 4 * (kb & 1)) * GT;
            const uint32_t SV   = (3 + 4 * (kb & 1)) * GT;
            const uint32_t sKhi = sb + 2 * SK;
            const uint32_t sKlo = sKhi + 2 * GT;
            const uint32_t sVhi = sb + 2 * SV;
            const uint32_t sVlo = sVhi + 2 * GT;

            // ---- Phase 1: S[32 x 64] = Qh*Kh + Qh*Kl ----
            float s[2][8][4];
#pragma unroll
            for (int mi = 0; mi < 2; mi++)
#pragma unroll
                for (int nt = 0; nt < 8; nt++)
#pragma unroll
                    for (int e = 0; e < 4; e++) s[mi][nt][e] = 0.0f;

#pragma unroll
            for (int ks = 0; ks < 4; ks++) {
                const int kk = ks * 16;
                uint32_t bh[4][4], bl[4][4];
#pragma unroll
                for (int j = 0; j < 4; j++) {
                    const int brow = nc0 + j * 16 + (q >> 1) * 8 + l8;
                    const int bcol = kk + (q & 1) * 8;
                    ldsm_x4(bh[j], sKhi + 2 * (brow * GS + bcol));
                    ldsm_x4(bl[j], sKlo + 2 * (brow * GS + bcol));
                }
                // pass hh
#pragma unroll
                for (int mi = 0; mi < 2; mi++)
#pragma unroll
                    for (int j = 0; j < 4; j++) {
                        mma_f16(s[mi][2 * j],     qfh[ks][mi], bh[j]);
                        mma_f16(s[mi][2 * j + 1], qfh[ks][mi], bh[j] + 2);
                    }
                // pass hl
#pragma unroll
                for (int mi = 0; mi < 2; mi++)
#pragma unroll
                    for (int j = 0; j < 4; j++) {
                        mma_f16(s[mi][2 * j],     qfh[ks][mi], bl[j]);
                        mma_f16(s[mi][2 * j + 1], qfh[ks][mi], bl[j] + 2);
                    }
            }

            // Diagonal-block causal mask: keep col <= row
            if (kb == qb) {
#pragma unroll
                for (int mi = 0; mi < 2; mi++) {
                    const int r0 = m0 + mi * 16 + g, r1 = r0 + 8;
#pragma unroll
                    for (int nt = 0; nt < 8; nt++) {
                        const int c0 = nc0 + nt * 8 + 2 * tq;
                        if (c0     > r0) s[mi][nt][0] = 0.0f;
                        if (c0 + 1 > r0) s[mi][nt][1] = 0.0f;
                        if (c0     > r1) s[mi][nt][2] = 0.0f;
                        if (c0 + 1 > r1) s[mi][nt][3] = 0.0f;
                    }
                }
            }

            // ---- Phase 2: O += Sh*Vh + Sh*Vl  (S truncated to fp16) ----
#pragma unroll
            for (int kc = 0; kc < 4; kc++) {
                uint32_t ah[2][4];
#pragma unroll
                for (int mi = 0; mi < 2; mi++) {
                    ah[mi][0] = pack2_f16(s[mi][2 * kc][0],     s[mi][2 * kc][1]);
                    ah[mi][1] = pack2_f16(s[mi][2 * kc][2],     s[mi][2 * kc][3]);
                    ah[mi][2] = pack2_f16(s[mi][2 * kc + 1][0], s[mi][2 * kc + 1][1]);
                    ah[mi][3] = pack2_f16(s[mi][2 * kc + 1][2], s[mi][2 * kc + 1][3]);
                }
                const int vr = nc0 + kc * 16 + (q & 1) * 8 + l8;
                uint32_t bh[4][4], bl[4][4];
#pragma unroll
                for (int dg = 0; dg < 4; dg++) {
                    const int vcol = dg * 16 + (q >> 1) * 8;
                    ldsm_x4_t(bh[dg], sVhi + 2 * (vr * GS + vcol));
                    ldsm_x4_t(bl[dg], sVlo + 2 * (vr * GS + vcol));
                }
                // pass hh
#pragma unroll
                for (int mi = 0; mi < 2; mi++)
#pragma unroll
                    for (int dg = 0; dg < 4; dg++) {
                        mma_f16(o[mi][2 * dg],     ah[mi], bh[dg]);
                        mma_f16(o[mi][2 * dg + 1], ah[mi], bh[dg] + 2);
                    }
                // pass hl
#pragma unroll
                for (int mi = 0; mi < 2; mi++)
#pragma unroll
                    for (int dg = 0; dg < 4; dg++) {
                        mma_f16(o[mi][2 * dg],     ah[mi], bl[dg]);
                        mma_f16(o[mi][2 * dg + 1], ah[mi], bl[dg] + 2);
                    }
            }
        }
    }

    // ---- Reduce O partials across n-half warp pairs (overlay dead smem) ----
    __syncthreads();
    float* red = (float*)sm;              // 32 KB overlay (Q + K0 tiles, dead)
    if (nh == 1) {
#pragma unroll
        for (int mi = 0; mi < 2; mi++)
#pragma unroll
            for (int ni = 0; ni < 8; ni++) {
                const int col = ni * 8 + 2 * tq;
                const int row = m0 + mi * 16 + g;
                float2 v0 = {o[mi][ni][0], o[mi][ni][1]};
                float2 v1 = {o[mi][ni][2], o[mi][ni][3]};
                *(float2*)&red[row * 64 + col]       = v0;
                *(float2*)&red[(row + 8) * 64 + col] = v1;
            }
    }
    __syncthreads();

    if (nh == 0) {
#pragma unroll
        for (int mi = 0; mi < 2; mi++)
#pragma unroll
            for (int ni = 0; ni < 8; ni++) {
                const int col = ni * 8 + 2 * tq;
                const int row = m0 + mi * 16 + g;
                float2 v0 = *(const float2*)&red[row * 64 + col];
                float2 v1 = *(const float2*)&red[(row + 8) * 64 + col];
                const float c00 = o[mi][ni][0] + v0.x, c01 = o[mi][ni][1] + v0.y;
                const float c10 = o[mi][ni][2] + v1.x, c11 = o[mi][ni][3] + v1.y;
                const int gc = hoff + col;
                const size_t r0 = (size_t)(qrow0 + row) * DMODEL + gc;
                const size_t r1 = (size_t)(qrow0 + row + 8) * DMODEL + gc;
                *(uint32_t*)&Ohi[r0] = pack2_bf16(c00, c01);
                *(uint32_t*)&Olo[r0] = pack2_bf16(c00 - bf16_hi(c00), c01 - bf16_hi(c01));
                *(uint32_t*)&Ohi[r1] = pack2_bf16(c10, c11);
                *(uint32_t*)&Olo[r1] = pack2_bf16(c10 - bf16_hi(c10), c11 - bf16_hi(c11));
            }
    }
}

// ---------------------------------------------------------------------------
// Launch
// ---------------------------------------------------------------------------
extern "C" void kernel_launch(void* const* d_in, const int* in_sizes, int n_in,
                              void* d_out, int out_size)
{
    const float* x    = (const float*)d_in[0];
    const float* wq_w = (const float*)d_in[1];
    const float* wq_b = (const float*)d_in[2];
    const float* wk_w = (const float*)d_in[3];
    const float* wk_b = (const float*)d_in[4];
    const float* wv_w = (const float*)d_in[5];
    const float* wv_b = (const float*)d_in[6];
    const float* wo_w = (const float*)d_in[7];
    const float* wo_b = (const float*)d_in[8];
    float* out = (float*)d_out;

    __nv_bfloat16 *xhi, *xlo, *whi, *wlo;
    __nv_bfloat16 *Qhi, *Qlo, *Khi, *Klo, *Vhi, *Vlo, *AOhi, *AOlo;
    cudaGetSymbolAddress((void**)&xhi,  g_xhi);
    cudaGetSymbolAddress((void**)&xlo,  g_xlo);
    cudaGetSymbolAddress((void**)&whi,  g_whi);
    cudaGetSymbolAddress((void**)&wlo,  g_wlo);
    cudaGetSymbolAddress((void**)&Qhi,  g_Qhi);
    cudaGetSymbolAddress((void**)&Qlo,  g_Qlo);
    cudaGetSymbolAddress((void**)&Khi,  g_Khi);
    cudaGetSymbolAddress((void**)&Klo,  g_Klo);
    cudaGetSymbolAddress((void**)&Vhi,  g_Vhi);
    cudaGetSymbolAddress((void**)&Vlo,  g_Vlo);
    cudaGetSymbolAddress((void**)&AOhi, g_AOhi);
    cudaGetSymbolAddress((void**)&AOlo, g_AOlo);

    cudaFuncSetAttribute(mma_gemm_kernel,
                         cudaFuncAttributeMaxDynamicSharedMemorySize, GEMM_SMEM_B);
    cudaFuncSetAttribute(mma_attn_kernel,
                         cudaFuncAttributeMaxDynamicSharedMemorySize, ATTN_SMEM_B);

    const size_t WW = (size_t)DMODEL * DMODEL;

    split_kernel<<<(MTOT * DMODEL / 4 + 255) / 256, 256>>>(x, xhi, xlo, MTOT * DMODEL / 4);
    {
        dim3 sgrid(((int)WW / 4 + 255) / 256, 4);
        split4_kernel<<<sgrid, 256>>>(wq_w, wk_w, wv_w, wo_w, whi, wlo, (int)WW / 4);
    }

    // Fused Q/K/V projections (mode 1 -> fp16 split outputs)
    dim3 gqkv(DMODEL / 128, MTOT / 256, 3);
    mma_gemm_kernel<<<gqkv, 256, GEMM_SMEM_B>>>(
        xhi, xlo, whi, wlo, wq_b, wk_b, wv_b,
        Qhi, Qlo, Khi, Klo, Vhi, Vlo, nullptr,
        MTOT, DMODEL, DMODEL, 1);

    dim3 agrid(SEQ / 128, NH, BATCH);
    mma_attn_kernel<<<agrid, 256, ATTN_SMEM_B>>>(Qhi, Khi, Klo, Vhi, Vlo, AOhi, AOlo);

    dim3 ggrid(DMODEL / 128, MTOT / 256, 1);
    mma_gemm_kernel<<<ggrid, 256, GEMM_SMEM_B>>>(
        AOhi, AOlo, whi + 3 * WW, wlo + 3 * WW, wo_b, nullptr, nullptr,
        nullptr, nullptr, nullptr, nullptr, nullptr, nullptr, out,
        MTOT, DMODEL, DMODEL, 0);
}